// round 1
// baseline (speedup 1.0000x reference)
#include <cuda_runtime.h>
#include <math.h>

#define EMB   2048
#define NQH   32
#define NKV   8
#define HD    64
#define BB    2
#define TT    2048
#define KVD   (NKV*HD)   // 512
#define MTOT  (BB*TT)    // 4096

// Scratch (no allocations allowed)
__device__ float g_q[(size_t)BB*TT*EMB];   // [B,T,NQH,HD]
__device__ float g_k[(size_t)BB*TT*KVD];   // [B,T,NKV,HD]
__device__ float g_v[(size_t)BB*TT*KVD];   // [B,T,NKV,HD]
__device__ float g_y[(size_t)BB*TT*EMB];   // [B,T,NQH,HD]

// ---------------------------------------------------------------------------
// NT GEMM: C[m][n] = sum_k A[m][k]*W[n][k] + bias[n]
// A: MxK row-major, W: NxK row-major. M%64==0, N%64==0, K%16==0.
// ---------------------------------------------------------------------------
__global__ __launch_bounds__(256)
void gemm_nt_bias(const float* __restrict__ A, const float* __restrict__ W,
                  const float* __restrict__ bias, float* __restrict__ C,
                  int M, int N, int K)
{
    const int BM = 64, BN = 64, BK = 16;
    __shared__ float a_s[BK][BM + 1];
    __shared__ float b_s[BK][BN + 1];

    const int bm  = blockIdx.y * BM;
    const int bn  = blockIdx.x * BN;
    const int tid = threadIdx.x;
    const int tm  = (tid >> 4) * 4;   // 0..60
    const int tn  = (tid & 15) * 4;   // 0..60

    // loader mapping: 64 rows, 4 threads/row, 4 consecutive floats each
    const int lr = tid >> 2;          // 0..63
    const int lk = (tid & 3) * 4;     // 0,4,8,12

    float acc[4][4];
#pragma unroll
    for (int i = 0; i < 4; i++)
#pragma unroll
        for (int j = 0; j < 4; j++) acc[i][j] = 0.f;

    for (int k0 = 0; k0 < K; k0 += BK) {
        float4 av = *(const float4*)(A + (size_t)(bm + lr) * K + k0 + lk);
        float4 bv = *(const float4*)(W + (size_t)(bn + lr) * K + k0 + lk);
        a_s[lk + 0][lr] = av.x; a_s[lk + 1][lr] = av.y;
        a_s[lk + 2][lr] = av.z; a_s[lk + 3][lr] = av.w;
        b_s[lk + 0][lr] = bv.x; b_s[lk + 1][lr] = bv.y;
        b_s[lk + 2][lr] = bv.z; b_s[lk + 3][lr] = bv.w;
        __syncthreads();

#pragma unroll
        for (int kk = 0; kk < BK; kk++) {
            float af[4], bf[4];
#pragma unroll
            for (int i = 0; i < 4; i++) af[i] = a_s[kk][tm + i];
#pragma unroll
            for (int j = 0; j < 4; j++) bf[j] = b_s[kk][tn + j];
#pragma unroll
            for (int i = 0; i < 4; i++)
#pragma unroll
                for (int j = 0; j < 4; j++)
                    acc[i][j] += af[i] * bf[j];
        }
        __syncthreads();
    }

#pragma unroll
    for (int i = 0; i < 4; i++) {
        float* cp = C + (size_t)(bm + tm + i) * N + bn + tn;
#pragma unroll
        for (int j = 0; j < 4; j++)
            cp[j] = acc[i][j] + bias[bn + tn + j];
    }
}

// ---------------------------------------------------------------------------
// RoPE in-place on q [B,T,NQH,HD] (y=0) and k [B,T,NKV,HD] (y=1).
// Folds the attention scale 1/sqrt(64)=0.125 into q.
// ---------------------------------------------------------------------------
__global__ __launch_bounds__(256)
void rope_kernel(float* __restrict__ q, float* __restrict__ k)
{
    const bool  is_k = (blockIdx.y != 0);
    float*      p    = is_k ? k : q;
    const int   H    = is_k ? NKV : NQH;
    const long  n    = (long)BB * TT * H * 32;
    const long  i    = (long)blockIdx.x * blockDim.x + threadIdx.x;
    if (i >= n) return;

    const int  d    = (int)(i & 31);
    const long rest = i >> 5;
    const int  h    = (int)(rest % H);
    const long bt   = rest / H;
    const int  t    = (int)(bt % TT);

    // inv_freq = 10000^(-2d/64)
    const float inv = expf(d * (-2.0f / 64.0f) * 9.210340371976184f);
    float s, c;
    sincosf((float)t * inv, &s, &c);

    const size_t base = ((size_t)bt * H + h) * HD;
    const float x1 = p[base + d];
    const float x2 = p[base + d + 32];
    const float scale = is_k ? 1.0f : 0.125f;
    p[base + d]      = (x1 * c - x2 * s) * scale;
    p[base + d + 32] = (x2 * c + x1 * s) * scale;
}

// ---------------------------------------------------------------------------
// Causal flash attention, fp32 online softmax.
// grid: (TT/64, NQH, BB), 256 threads.
// Thread (r = tid/4, g = tid%4): owns S[r][16g..16g+15] and O[r][16g..16g+15].
// q row kept in registers; P overwrites the K smem tile.
// ---------------------------------------------------------------------------
__global__ __launch_bounds__(256)
void attn_kernel(const float* __restrict__ q, const float* __restrict__ k,
                 const float* __restrict__ v, float* __restrict__ y)
{
    const int qt = blockIdx.x;
    const int h  = blockIdx.y;
    const int b  = blockIdx.z;
    const int hk = h >> 2;

    const int tid = threadIdx.x;
    const int r   = tid >> 2;       // 0..63
    const int g   = tid & 3;
    const int c0  = g * 16;

    __shared__ float k_s[64][65];   // also reused for P
    __shared__ float v_s[64][65];

    const int qrow = qt * 64 + r;
    float qreg[64];
    {
        const float* qp = q + (((size_t)b * TT + qrow) * NQH + h) * HD;
#pragma unroll
        for (int d = 0; d < 64; d += 4) {
            float4 t4 = *(const float4*)(qp + d);
            qreg[d] = t4.x; qreg[d+1] = t4.y; qreg[d+2] = t4.z; qreg[d+3] = t4.w;
        }
    }

    float m = -INFINITY, l = 0.f;
    float o[16];
#pragma unroll
    for (int i = 0; i < 16; i++) o[i] = 0.f;

    for (int kt = 0; kt <= qt; kt++) {
        // stage K, V tiles: 64 rows, 4 threads/row, 16 floats each
        {
            const int lr = tid >> 2;
            const int lc = (tid & 3) * 16;
            const size_t row = ((size_t)b * TT + kt * 64 + lr) * NKV + hk;
            const float* kp = k + row * HD + lc;
            const float* vp = v + row * HD + lc;
#pragma unroll
            for (int i = 0; i < 16; i += 4) {
                float4 t4 = *(const float4*)(kp + i);
                k_s[lr][lc+i] = t4.x; k_s[lr][lc+i+1] = t4.y;
                k_s[lr][lc+i+2] = t4.z; k_s[lr][lc+i+3] = t4.w;
                float4 u4 = *(const float4*)(vp + i);
                v_s[lr][lc+i] = u4.x; v_s[lr][lc+i+1] = u4.y;
                v_s[lr][lc+i+2] = u4.z; v_s[lr][lc+i+3] = u4.w;
            }
        }
        __syncthreads();

        // S[r][c0+j] = q[r] . k[c0+j]
        float s[16];
#pragma unroll
        for (int j = 0; j < 16; j++) {
            float acc = 0.f;
#pragma unroll
            for (int d = 0; d < 64; d++)
                acc += qreg[d] * k_s[c0 + j][d];
            s[j] = acc;
        }

        if (kt == qt) {
#pragma unroll
            for (int j = 0; j < 16; j++)
                if (c0 + j > r) s[j] = -INFINITY;
        }

        // online softmax (quad = 4 threads sharing row r are lanes r*4+g)
        float tmax = s[0];
#pragma unroll
        for (int j = 1; j < 16; j++) tmax = fmaxf(tmax, s[j]);
        tmax = fmaxf(tmax, __shfl_xor_sync(0xffffffffu, tmax, 1));
        tmax = fmaxf(tmax, __shfl_xor_sync(0xffffffffu, tmax, 2));

        const float mnew  = fmaxf(m, tmax);
        const float alpha = expf(m - mnew);

        float psum = 0.f;
#pragma unroll
        for (int j = 0; j < 16; j++) {
            s[j] = expf(s[j] - mnew);
            psum += s[j];
        }
        psum += __shfl_xor_sync(0xffffffffu, psum, 1);
        psum += __shfl_xor_sync(0xffffffffu, psum, 2);

        l = l * alpha + psum;
        m = mnew;
#pragma unroll
        for (int i = 0; i < 16; i++) o[i] *= alpha;

        __syncthreads();                 // everyone done reading k_s
#pragma unroll
        for (int j = 0; j < 16; j++)     // P overwrites K tile
            k_s[r][c0 + j] = s[j];
        __syncthreads();

        // O[r][c0+i] += sum_c P[r][c] * V[c][c0+i]
#pragma unroll 4
        for (int c = 0; c < 64; c++) {
            const float p = k_s[r][c];
#pragma unroll
            for (int i = 0; i < 16; i++)
                o[i] += p * v_s[c][c0 + i];
        }
        __syncthreads();                 // before next tile load
    }

    const float inv_l = 1.f / l;
    float* yp = y + (((size_t)b * TT + qrow) * NQH + h) * HD + c0;
#pragma unroll
    for (int i = 0; i < 16; i++) yp[i] = o[i] * inv_l;
}

// ---------------------------------------------------------------------------
extern "C" void kernel_launch(void* const* d_in, const int* in_sizes, int n_in,
                              void* d_out, int out_size)
{
    const float* x  = (const float*)d_in[0];
    const float* Wq = (const float*)d_in[1];
    const float* bq = (const float*)d_in[2];
    const float* Wk = (const float*)d_in[3];
    const float* bk = (const float*)d_in[4];
    const float* Wv = (const float*)d_in[5];
    const float* bv = (const float*)d_in[6];
    const float* Wo = (const float*)d_in[7];
    const float* bo = (const float*)d_in[8];
    float* out = (float*)d_out;

    float *qp, *kp, *vp, *yp;
    cudaGetSymbolAddress((void**)&qp, g_q);
    cudaGetSymbolAddress((void**)&kp, g_k);
    cudaGetSymbolAddress((void**)&vp, g_v);
    cudaGetSymbolAddress((void**)&yp, g_y);

    // QKV projections
    gemm_nt_bias<<<dim3(EMB / 64, MTOT / 64), 256>>>(x, Wq, bq, qp, MTOT, EMB, EMB);
    gemm_nt_bias<<<dim3(KVD / 64, MTOT / 64), 256>>>(x, Wk, bk, kp, MTOT, KVD, EMB);
    gemm_nt_bias<<<dim3(KVD / 64, MTOT / 64), 256>>>(x, Wv, bv, vp, MTOT, KVD, EMB);

    // RoPE (q scaled by 1/sqrt(HD))
    {
        long nmax = (long)BB * TT * NQH * 32;
        int blocks = (int)((nmax + 255) / 256);
        rope_kernel<<<dim3(blocks, 2), 256>>>(qp, kp);
    }

    // Causal GQA flash attention
    attn_kernel<<<dim3(TT / 64, NQH, BB), 256>>>(qp, kp, vp, yp);

    // Output projection
    gemm_nt_bias<<<dim3(EMB / 64, MTOT / 64), 256>>>(yp, Wo, bo, out, MTOT, EMB, EMB);
}

// round 3
// speedup vs baseline: 2.2315x; 2.2315x over previous
#include <cuda_runtime.h>
#include <math.h>
#include <stdint.h>

#define EMB   2048
#define NQH   32
#define NKV   8
#define HD    64
#define BB    2
#define TT    2048
#define KVD   (NKV*HD)   // 512
#define MTOT  (BB*TT)    // 4096

// Scratch (no allocations allowed)
__device__ float g_q[(size_t)BB*TT*EMB];   // [B,T,NQH,HD]
__device__ float g_k[(size_t)BB*TT*KVD];   // [B,T,NKV,HD]
__device__ float g_v[(size_t)BB*TT*KVD];   // [B,T,NKV,HD]
__device__ float g_y[(size_t)BB*TT*EMB];   // [B,T,NQH,HD]

static __device__ __forceinline__ uint32_t f2tf(float f) {
    uint32_t u;
    asm("cvt.rna.tf32.f32 %0, %1;" : "=r"(u) : "f"(f));
    return u;
}

static __device__ __forceinline__ void mma_tf32(float c[4], const uint32_t a[4],
                                                const uint32_t b[2]) {
    asm volatile(
        "mma.sync.aligned.m16n8k8.row.col.f32.tf32.tf32.f32 "
        "{%0,%1,%2,%3}, {%4,%5,%6,%7}, {%8,%9}, {%0,%1,%2,%3};"
        : "+f"(c[0]), "+f"(c[1]), "+f"(c[2]), "+f"(c[3])
        : "r"(a[0]), "r"(a[1]), "r"(a[2]), "r"(a[3]), "r"(b[0]), "r"(b[1]));
}

// ===========================================================================
// HMMA tf32 GEMM: C[m][n] = sum_k A[m][k]*W[n][k] + bias[n]
// A: MxK row-major (m,k). W: NxK row-major => B fragment (k,n) col-major view.
// Tile 128x128, BK=32, 8 warps as 2(m) x 4(n), warp tile 64x32.
// Operands staged in smem PRE-PACKED into mma fragment layout:
//   A frag float4/lane, B frag float2/lane.
// ===========================================================================
#define BK 32
#define STAGE_FLOATS 8192               // A 4096 + B 4096
#define GEMM_SMEM (2 * STAGE_FLOATS * 4)  // 65536 bytes

__global__ __launch_bounds__(256)
void gemm_tc(const float* __restrict__ A, const float* __restrict__ W,
             const float* __restrict__ bias, float* __restrict__ C,
             int M, int N, int K)
{
    extern __shared__ float sm[];
    const int tid = threadIdx.x;
    const int wid = tid >> 5;
    const int lane = tid & 31;
    const int wm = wid >> 2;          // 0..1
    const int wn = wid & 3;           // 0..3
    const int bm = blockIdx.y * 128;
    const int bn = blockIdx.x * 128;

    const int NCH = K / BK;

    float acc[4][4][4];
#pragma unroll
    for (int i = 0; i < 4; i++)
#pragma unroll
        for (int j = 0; j < 4; j++)
#pragma unroll
            for (int r = 0; r < 4; r++) acc[i][j][r] = 0.f;

    // staging indices for this thread (4 float4 of A, 4 float4 of W)
    // idx = tid + 256*i : row = idx>>3 (0..127), c4 = idx&7 (col0 = 4*c4)
    // A frag addr  (floats): ((mtile*4 + k8)*32 + lane)*4 + reg
    //    mtile=row>>4, r=row&15, lane=((r&7)<<2)|(c&3), reg=(r>>3)+(((c>>2)&1)<<1)
    // B frag addr  (floats): 4096 + ((ntile*4 + k8)*32 + lane)*2 + reg
    //    ntile=row>>3, lane=((row&7)<<2)|(c&3), reg=(c>>2)&1
    int a_dst[4], b_dst[4];
#pragma unroll
    for (int i = 0; i < 4; i++) {
        const int idx = tid + 256 * i;
        const int row = idx >> 3;
        const int c0 = (idx & 7) * 4;
        {
            const int r = row & 15, mtile = row >> 4, k8 = c0 >> 3;
            a_dst[i] = ((mtile * 4 + k8) * 32 + (((r & 7) << 2) | (c0 & 3))) * 4 + (r >> 3)
                     + ((((c0 >> 2) & 1)) << 1);
        }
        {
            const int ntile = row >> 3, k8 = c0 >> 3;
            b_dst[i] = 4096 + ((ntile * 4 + k8) * 32 + (((row & 7) << 2) | (c0 & 3))) * 2
                     + ((c0 >> 2) & 1);
        }
    }
    // NB: within a float4 (c0..c0+3): k8 and (c>>2)&1 are constant, lane +0..3.
    // A: addr stride 4 floats; B: addr stride 2 floats.

    auto stage = [&](const float4* av, const float4* wv, int s) {
        float* dst = sm + s * STAGE_FLOATS;
#pragma unroll
        for (int i = 0; i < 4; i++) {
            float4 v = av[i];
            dst[a_dst[i] + 0]  = __uint_as_float(f2tf(v.x));
            dst[a_dst[i] + 4]  = __uint_as_float(f2tf(v.y));
            dst[a_dst[i] + 8]  = __uint_as_float(f2tf(v.z));
            dst[a_dst[i] + 12] = __uint_as_float(f2tf(v.w));
            float4 w = wv[i];
            dst[b_dst[i] + 0] = __uint_as_float(f2tf(w.x));
            dst[b_dst[i] + 2] = __uint_as_float(f2tf(w.y));
            dst[b_dst[i] + 4] = __uint_as_float(f2tf(w.z));
            dst[b_dst[i] + 6] = __uint_as_float(f2tf(w.w));
        }
    };

    auto gload = [&](int ch, float4* av, float4* wv) {
        const int k0 = ch * BK;
#pragma unroll
        for (int i = 0; i < 4; i++) {
            const int idx = tid + 256 * i;
            const int row = idx >> 3;
            const int c0 = (idx & 7) * 4;
            av[i] = *(const float4*)(A + (size_t)(bm + row) * K + k0 + c0);
            wv[i] = *(const float4*)(W + (size_t)(bn + row) * K + k0 + c0);
        }
    };

    float4 av[4], wv[4];
    gload(0, av, wv);
    stage(av, wv, 0);
    __syncthreads();

    for (int c = 0; c < NCH; c++) {
        const int s = c & 1;
        const bool more = (c + 1 < NCH);
        if (more) gload(c + 1, av, wv);

        const float* st = sm + s * STAGE_FLOATS;
#pragma unroll
        for (int k8 = 0; k8 < 4; k8++) {
            uint32_t afr[4][4];
            uint32_t bfr[4][2];
#pragma unroll
            for (int mt = 0; mt < 4; mt++) {
                const int mtile = wm * 4 + mt;
                const float4 f = *(const float4*)(st + ((mtile * 4 + k8) * 32 + lane) * 4);
                afr[mt][0] = __float_as_uint(f.x); afr[mt][1] = __float_as_uint(f.y);
                afr[mt][2] = __float_as_uint(f.z); afr[mt][3] = __float_as_uint(f.w);
            }
#pragma unroll
            for (int nt = 0; nt < 4; nt++) {
                const int ntile = wn * 4 + nt;
                const float2 f = *(const float2*)(st + 4096 + ((ntile * 4 + k8) * 32 + lane) * 2);
                bfr[nt][0] = __float_as_uint(f.x); bfr[nt][1] = __float_as_uint(f.y);
            }
#pragma unroll
            for (int mt = 0; mt < 4; mt++)
#pragma unroll
                for (int nt = 0; nt < 4; nt++)
                    mma_tf32(acc[mt][nt], afr[mt], bfr[nt]);
        }

        if (more) stage(av, wv, s ^ 1);
        __syncthreads();
    }

    // epilogue: c0:(row,col) c1:(row,col+1) c2:(row+8,col) c3:(row+8,col+1)
    const int rbase = bm + wm * 64 + (lane >> 2);
    const int cbase = bn + wn * 32 + (lane & 3) * 2;
#pragma unroll
    for (int mt = 0; mt < 4; mt++) {
#pragma unroll
        for (int nt = 0; nt < 4; nt++) {
            const int row = rbase + mt * 16;
            const int col = cbase + nt * 8;
            const float2 bb = *(const float2*)(bias + col);
            float2 o0 = make_float2(acc[mt][nt][0] + bb.x, acc[mt][nt][1] + bb.y);
            float2 o1 = make_float2(acc[mt][nt][2] + bb.x, acc[mt][nt][3] + bb.y);
            *(float2*)(C + (size_t)row * N + col) = o0;
            *(float2*)(C + (size_t)(row + 8) * N + col) = o1;
        }
    }
}

// ---------------------------------------------------------------------------
// RoPE in-place on q (y=0, scaled by 0.125) and k (y=1).
// ---------------------------------------------------------------------------
__global__ __launch_bounds__(256)
void rope_kernel(float* __restrict__ q, float* __restrict__ k)
{
    const bool  is_k = (blockIdx.y != 0);
    float*      p    = is_k ? k : q;
    const int   H    = is_k ? NKV : NQH;
    const long  n    = (long)BB * TT * H * 32;
    const long  i    = (long)blockIdx.x * blockDim.x + threadIdx.x;
    if (i >= n) return;

    const int  d    = (int)(i & 31);
    const long rest = i >> 5;
    const int  h    = (int)(rest % H);
    const long bt   = rest / H;
    const int  t    = (int)(bt % TT);

    const float inv = expf(d * (-2.0f / 64.0f) * 9.210340371976184f);
    float s, c;
    sincosf((float)t * inv, &s, &c);

    const size_t base = ((size_t)bt * H + h) * HD;
    const float x1 = p[base + d];
    const float x2 = p[base + d + 32];
    const float scale = is_k ? 1.0f : 0.125f;
    p[base + d]      = (x1 * c - x2 * s) * scale;
    p[base + d + 32] = (x2 * c + x1 * s) * scale;
}

// ---------------------------------------------------------------------------
// Causal flash attention, fp32 online softmax, vectorized LDS.
// Thread (r = tid/4, g = tid%4) owns interleaved cols {4j+g} of S and O.
// ---------------------------------------------------------------------------
__global__ __launch_bounds__(256)
void attn_kernel(const float* __restrict__ q, const float* __restrict__ k,
                 const float* __restrict__ v, float* __restrict__ y)
{
    const int qt = blockIdx.x;
    const int h  = blockIdx.y;
    const int b  = blockIdx.z;
    const int hk = h >> 2;

    const int tid = threadIdx.x;
    const int r   = tid >> 2;       // 0..63
    const int g   = tid & 3;

    __shared__ float k_s [64][68];  // K rows; reused for P
    __shared__ float v_sT[64][68];  // transposed V: [d][token]

    const int qrow = qt * 64 + r;
    float qreg[64];
    {
        const float* qp = q + (((size_t)b * TT + qrow) * NQH + h) * HD;
#pragma unroll
        for (int d = 0; d < 64; d += 4) {
            float4 t4 = *(const float4*)(qp + d);
            qreg[d] = t4.x; qreg[d+1] = t4.y; qreg[d+2] = t4.z; qreg[d+3] = t4.w;
        }
    }

    float m = -INFINITY, l = 0.f;
    float o[16];
#pragma unroll
    for (int i = 0; i < 16; i++) o[i] = 0.f;

    for (int kt = 0; kt <= qt; kt++) {
        {
            const int lr = tid >> 2;
            const int lc = (tid & 3) * 16;
            const size_t row = ((size_t)b * TT + kt * 64 + lr) * NKV + hk;
            const float* kp = k + row * HD + lc;
            const float* vp = v + row * HD + lc;
#pragma unroll
            for (int i = 0; i < 16; i += 4) {
                float4 t4 = *(const float4*)(kp + i);
                *(float4*)&k_s[lr][lc + i] = t4;
                float4 u4 = *(const float4*)(vp + i);
                v_sT[lc + i + 0][lr] = u4.x;
                v_sT[lc + i + 1][lr] = u4.y;
                v_sT[lc + i + 2][lr] = u4.z;
                v_sT[lc + i + 3][lr] = u4.w;
            }
        }
        __syncthreads();

        float s[16];
#pragma unroll
        for (int j = 0; j < 16; j++) {
            const float4* krow = (const float4*)&k_s[4 * j + g][0];
            float acc = 0.f;
#pragma unroll
            for (int d4 = 0; d4 < 16; d4++) {
                const float4 kv = krow[d4];
                acc += qreg[4*d4+0] * kv.x + qreg[4*d4+1] * kv.y
                     + qreg[4*d4+2] * kv.z + qreg[4*d4+3] * kv.w;
            }
            s[j] = acc;
        }

        if (kt == qt) {
#pragma unroll
            for (int j = 0; j < 16; j++)
                if (4 * j + g > r) s[j] = -INFINITY;
        }

        float tmax = s[0];
#pragma unroll
        for (int j = 1; j < 16; j++) tmax = fmaxf(tmax, s[j]);
        tmax = fmaxf(tmax, __shfl_xor_sync(0xffffffffu, tmax, 1));
        tmax = fmaxf(tmax, __shfl_xor_sync(0xffffffffu, tmax, 2));

        const float mnew  = fmaxf(m, tmax);
        const float alpha = expf(m - mnew);

        float psum = 0.f;
#pragma unroll
        for (int j = 0; j < 16; j++) {
            s[j] = expf(s[j] - mnew);
            psum += s[j];
        }
        psum += __shfl_xor_sync(0xffffffffu, psum, 1);
        psum += __shfl_xor_sync(0xffffffffu, psum, 2);

        l = l * alpha + psum;
        m = mnew;
#pragma unroll
        for (int i = 0; i < 16; i++) o[i] *= alpha;

        __syncthreads();
#pragma unroll
        for (int j = 0; j < 16; j++)
            k_s[r][4 * j + g] = s[j];
        __syncthreads();

        const float4* prow = (const float4*)&k_s[r][0];
#pragma unroll 4
        for (int c4 = 0; c4 < 16; c4++) {
            const float4 p4 = prow[c4];
#pragma unroll
            for (int i = 0; i < 16; i++) {
                const float4 v4 = *(const float4*)&v_sT[4 * i + g][4 * c4];
                o[i] += p4.x * v4.x + p4.y * v4.y + p4.z * v4.z + p4.w * v4.w;
            }
        }
        __syncthreads();
    }

    const float inv_l = 1.f / l;
    float* yp = y + (((size_t)b * TT + qrow) * NQH + h) * HD;
#pragma unroll
    for (int i = 0; i < 16; i++) yp[4 * i + g] = o[i] * inv_l;
}

// ---------------------------------------------------------------------------
extern "C" void kernel_launch(void* const* d_in, const int* in_sizes, int n_in,
                              void* d_out, int out_size)
{
    const float* x  = (const float*)d_in[0];
    const float* Wq = (const float*)d_in[1];
    const float* bq = (const float*)d_in[2];
    const float* Wk = (const float*)d_in[3];
    const float* bk = (const float*)d_in[4];
    const float* Wv = (const float*)d_in[5];
    const float* bv = (const float*)d_in[6];
    const float* Wo = (const float*)d_in[7];
    const float* bo = (const float*)d_in[8];
    float* out = (float*)d_out;

    float *qp, *kp, *vp, *yp;
    cudaGetSymbolAddress((void**)&qp, g_q);
    cudaGetSymbolAddress((void**)&kp, g_k);
    cudaGetSymbolAddress((void**)&vp, g_v);
    cudaGetSymbolAddress((void**)&yp, g_y);

    cudaFuncSetAttribute(gemm_tc, cudaFuncAttributeMaxDynamicSharedMemorySize,
                         GEMM_SMEM);

    // QKV projections (HMMA tf32)
    gemm_tc<<<dim3(EMB / 128, MTOT / 128), 256, GEMM_SMEM>>>(x, Wq, bq, qp, MTOT, EMB, EMB);
    gemm_tc<<<dim3(KVD / 128, MTOT / 128), 256, GEMM_SMEM>>>(x, Wk, bk, kp, MTOT, KVD, EMB);
    gemm_tc<<<dim3(KVD / 128, MTOT / 128), 256, GEMM_SMEM>>>(x, Wv, bv, vp, MTOT, KVD, EMB);

    // RoPE (q scaled by 1/sqrt(HD))
    {
        long nmax = (long)BB * TT * NQH * 32;
        int blocks = (int)((nmax + 255) / 256);
        rope_kernel<<<dim3(blocks, 2), 256>>>(qp, kp);
    }

    // Causal GQA flash attention
    attn_kernel<<<dim3(TT / 64, NQH, BB), 256>>>(qp, kp, vp, yp);

    // Output projection (HMMA tf32)
    gemm_tc<<<dim3(EMB / 128, MTOT / 128), 256, GEMM_SMEM>>>(yp, Wo, bo, out, MTOT, EMB, EMB);
}

// round 4
// speedup vs baseline: 5.0185x; 2.2489x over previous
#include <cuda_runtime.h>
#include <math.h>
#include <stdint.h>

#define EMB   2048
#define NQH   32
#define NKV   8
#define HD    64
#define BB    2
#define TT    2048
#define KVD   (NKV*HD)   // 512
#define MTOT  (BB*TT)    // 4096

// Scratch (no allocations allowed)
__device__ float g_q[(size_t)BB*TT*EMB];   // [B,T,NQH,HD]
__device__ float g_k[(size_t)BB*TT*KVD];   // [B,T,NKV,HD]
__device__ float g_v[(size_t)BB*TT*KVD];   // [B,T,NKV,HD]
__device__ float g_y[(size_t)BB*TT*EMB];   // [B,T,NQH,HD]

static __device__ __forceinline__ uint32_t f2tf(float f) {
    uint32_t u;
    asm("cvt.rna.tf32.f32 %0, %1;" : "=r"(u) : "f"(f));
    return u;
}
static __device__ __forceinline__ float tf(float f) {
    return __uint_as_float(f2tf(f));
}

static __device__ __forceinline__ void mma_tf32(float c[4], const uint32_t a[4],
                                                uint32_t b0, uint32_t b1) {
    asm volatile(
        "mma.sync.aligned.m16n8k8.row.col.f32.tf32.tf32.f32 "
        "{%0,%1,%2,%3}, {%4,%5,%6,%7}, {%8,%9}, {%0,%1,%2,%3};"
        : "+f"(c[0]), "+f"(c[1]), "+f"(c[2]), "+f"(c[3])
        : "r"(a[0]), "r"(a[1]), "r"(a[2]), "r"(a[3]), "r"(b0), "r"(b1));
}

// ===========================================================================
// HMMA tf32 GEMM: C[m][n] = sum_k A[m][k]*W[n][k] + bias[n]  (as in R3)
// ===========================================================================
#define BK 32
#define STAGE_FLOATS 8192
#define GEMM_SMEM (2 * STAGE_FLOATS * 4)

__global__ __launch_bounds__(256)
void gemm_tc(const float* __restrict__ A, const float* __restrict__ W,
             const float* __restrict__ bias, float* __restrict__ C,
             int M, int N, int K)
{
    extern __shared__ float sm[];
    const int tid = threadIdx.x;
    const int wid = tid >> 5;
    const int lane = tid & 31;
    const int wm = wid >> 2;
    const int wn = wid & 3;
    const int bm = blockIdx.y * 128;
    const int bn = blockIdx.x * 128;

    const int NCH = K / BK;

    float acc[4][4][4];
#pragma unroll
    for (int i = 0; i < 4; i++)
#pragma unroll
        for (int j = 0; j < 4; j++)
#pragma unroll
            for (int r = 0; r < 4; r++) acc[i][j][r] = 0.f;

    int a_dst[4], b_dst[4];
#pragma unroll
    for (int i = 0; i < 4; i++) {
        const int idx = tid + 256 * i;
        const int row = idx >> 3;
        const int c0 = (idx & 7) * 4;
        {
            const int r = row & 15, mtile = row >> 4, k8 = c0 >> 3;
            a_dst[i] = ((mtile * 4 + k8) * 32 + (((r & 7) << 2) | (c0 & 3))) * 4 + (r >> 3)
                     + ((((c0 >> 2) & 1)) << 1);
        }
        {
            const int ntile = row >> 3, k8 = c0 >> 3;
            b_dst[i] = 4096 + ((ntile * 4 + k8) * 32 + (((row & 7) << 2) | (c0 & 3))) * 2
                     + ((c0 >> 2) & 1);
        }
    }

    auto stage = [&](const float4* av, const float4* wv, int s) {
        float* dst = sm + s * STAGE_FLOATS;
#pragma unroll
        for (int i = 0; i < 4; i++) {
            float4 v = av[i];
            dst[a_dst[i] + 0]  = tf(v.x);
            dst[a_dst[i] + 4]  = tf(v.y);
            dst[a_dst[i] + 8]  = tf(v.z);
            dst[a_dst[i] + 12] = tf(v.w);
            float4 w = wv[i];
            dst[b_dst[i] + 0] = tf(w.x);
            dst[b_dst[i] + 2] = tf(w.y);
            dst[b_dst[i] + 4] = tf(w.z);
            dst[b_dst[i] + 6] = tf(w.w);
        }
    };

    auto gload = [&](int ch, float4* av, float4* wv) {
        const int k0 = ch * BK;
#pragma unroll
        for (int i = 0; i < 4; i++) {
            const int idx = tid + 256 * i;
            const int row = idx >> 3;
            const int c0 = (idx & 7) * 4;
            av[i] = *(const float4*)(A + (size_t)(bm + row) * K + k0 + c0);
            wv[i] = *(const float4*)(W + (size_t)(bn + row) * K + k0 + c0);
        }
    };

    float4 av[4], wv[4];
    gload(0, av, wv);
    stage(av, wv, 0);
    __syncthreads();

    for (int c = 0; c < NCH; c++) {
        const int s = c & 1;
        const bool more = (c + 1 < NCH);
        if (more) gload(c + 1, av, wv);

        const float* st = sm + s * STAGE_FLOATS;
#pragma unroll
        for (int k8 = 0; k8 < 4; k8++) {
            uint32_t afr[4][4];
            uint32_t bfr[4][2];
#pragma unroll
            for (int mt = 0; mt < 4; mt++) {
                const int mtile = wm * 4 + mt;
                const float4 f = *(const float4*)(st + ((mtile * 4 + k8) * 32 + lane) * 4);
                afr[mt][0] = __float_as_uint(f.x); afr[mt][1] = __float_as_uint(f.y);
                afr[mt][2] = __float_as_uint(f.z); afr[mt][3] = __float_as_uint(f.w);
            }
#pragma unroll
            for (int nt = 0; nt < 4; nt++) {
                const int ntile = wn * 4 + nt;
                const float2 f = *(const float2*)(st + 4096 + ((ntile * 4 + k8) * 32 + lane) * 2);
                bfr[nt][0] = __float_as_uint(f.x); bfr[nt][1] = __float_as_uint(f.y);
            }
#pragma unroll
            for (int mt = 0; mt < 4; mt++)
#pragma unroll
                for (int nt = 0; nt < 4; nt++)
                    mma_tf32(acc[mt][nt], afr[mt], bfr[nt][0], bfr[nt][1]);
        }

        if (more) stage(av, wv, s ^ 1);
        __syncthreads();
    }

    const int rbase = bm + wm * 64 + (lane >> 2);
    const int cbase = bn + wn * 32 + (lane & 3) * 2;
#pragma unroll
    for (int mt = 0; mt < 4; mt++) {
#pragma unroll
        for (int nt = 0; nt < 4; nt++) {
            const int row = rbase + mt * 16;
            const int col = cbase + nt * 8;
            const float2 bb = *(const float2*)(bias + col);
            float2 o0 = make_float2(acc[mt][nt][0] + bb.x, acc[mt][nt][1] + bb.y);
            float2 o1 = make_float2(acc[mt][nt][2] + bb.x, acc[mt][nt][3] + bb.y);
            *(float2*)(C + (size_t)row * N + col) = o0;
            *(float2*)(C + (size_t)(row + 8) * N + col) = o1;
        }
    }
}

// ---------------------------------------------------------------------------
// RoPE in-place on q (y=0, scaled by 0.125) and k (y=1).
// ---------------------------------------------------------------------------
__global__ __launch_bounds__(256)
void rope_kernel(float* __restrict__ q, float* __restrict__ k)
{
    const bool  is_k = (blockIdx.y != 0);
    float*      p    = is_k ? k : q;
    const int   H    = is_k ? NKV : NQH;
    const long  n    = (long)BB * TT * H * 32;
    const long  i    = (long)blockIdx.x * blockDim.x + threadIdx.x;
    if (i >= n) return;

    const int  d    = (int)(i & 31);
    const long rest = i >> 5;
    const int  h    = (int)(rest % H);
    const long bt   = rest / H;
    const int  t    = (int)(bt % TT);

    const float inv = expf(d * (-2.0f / 64.0f) * 9.210340371976184f);
    float s, c;
    sincosf((float)t * inv, &s, &c);

    const size_t base = ((size_t)bt * H + h) * HD;
    const float x1 = p[base + d];
    const float x2 = p[base + d + 32];
    const float scale = is_k ? 1.0f : 0.125f;
    p[base + d]      = (x1 * c - x2 * s) * scale;
    p[base + d + 32] = (x2 * c + x1 * s) * scale;
}

// ===========================================================================
// Tensor-core causal flash attention (tf32 HMMA).
// CTA = 128 threads (4 warps). Q tile 128 rows; key tiles of 64.
// Warp w owns q-row mtiles {2w, 2w+1} (16 rows each).
// smem: kf (4096 f, K B-frags paired), vf (4096 f, V B-frags paired),
//       pq (8448 f: Q A-frags in prologue, then P rows [128][66]).
// ===========================================================================
#define ATTN_SMEM ((4096 + 4096 + 8448) * 4)

// B-frag pack (paired n-tiles): element (n, k), n,k in [0,64)
static __device__ __forceinline__ int bpack_idx(int n, int k) {
    const int nt = n >> 3, k8 = k >> 3;
    const int ln = ((n & 7) << 2) | (k & 3);
    const int reg = (k >> 2) & 1;
    return (((((nt >> 1) * 8) + k8) * 32 + ln) << 2) + ((nt & 1) << 1) + reg;
}
// A-frag pack: element (r, c), r in [0,128), c in [0,64)
static __device__ __forceinline__ int apack_idx(int r, int c) {
    const int mt = r >> 4, k8 = c >> 3;
    const int ln = ((r & 7) << 2) | (c & 3);
    const int reg = ((r >> 3) & 1) | (((c >> 2) & 1) << 1);
    return (((mt * 8 + k8) * 32 + ln) << 2) + reg;
}

__global__ __launch_bounds__(128)
void attn_tc(const float* __restrict__ q, const float* __restrict__ k,
             const float* __restrict__ v, float* __restrict__ y)
{
    extern __shared__ float smf[];
    float* kf = smf;            // 4096
    float* vf = smf + 4096;     // 4096
    float* pq = smf + 8192;     // 8448

    const int qt = (gridDim.x - 1) - blockIdx.x;   // big tiles first
    const int h  = blockIdx.y;
    const int b  = blockIdx.z;
    const int hk = h >> 2;

    const int tid  = threadIdx.x;
    const int w    = tid >> 5;
    const int lane = tid & 31;
    const int lr   = lane >> 2;   // row within 8-group
    const int lc   = lane & 3;

    // ---- prologue: load+pack Q tile into pq, then to registers
#pragma unroll
    for (int i = 0; i < 16; i++) {
        const int idx4 = tid + 128 * i;
        const int r  = idx4 >> 4;
        const int c4 = (idx4 & 15) << 2;
        const float4 t = *(const float4*)(q + ((((size_t)b * TT) + qt * 128 + r) * NQH + h) * HD + c4);
        const int d = apack_idx(r, c4);
        pq[d + 0]  = tf(t.x);
        pq[d + 4]  = tf(t.y);
        pq[d + 8]  = tf(t.z);
        pq[d + 12] = tf(t.w);
    }
    __syncthreads();

    uint32_t qa[2][8][4];
#pragma unroll
    for (int mt = 0; mt < 2; mt++)
#pragma unroll
        for (int k8 = 0; k8 < 8; k8++) {
            const float4 f = *(const float4*)(pq + ((((2 * w + mt) * 8 + k8) * 32 + lane) << 2));
            qa[mt][k8][0] = __float_as_uint(f.x);
            qa[mt][k8][1] = __float_as_uint(f.y);
            qa[mt][k8][2] = __float_as_uint(f.z);
            qa[mt][k8][3] = __float_as_uint(f.w);
        }
    __syncthreads();   // pq now free for P

    float m[2][2], l[2][2];
    float o[2][8][4];
#pragma unroll
    for (int mt = 0; mt < 2; mt++) {
        m[mt][0] = -INFINITY; m[mt][1] = -INFINITY;
        l[mt][0] = 0.f;       l[mt][1] = 0.f;
#pragma unroll
        for (int nt = 0; nt < 8; nt++)
#pragma unroll
            for (int r = 0; r < 4; r++) o[mt][nt][r] = 0.f;
    }

    const int ktmax = 2 * qt + 1;
    for (int kt = 0; kt <= ktmax; kt++) {
        // ---- load + pack K, V tiles (all 128 threads)
#pragma unroll
        for (int i = 0; i < 8; i++) {
            const int idx4 = tid + 128 * i;
            const int tok = idx4 >> 4;
            const int c4  = (idx4 & 15) << 2;
            const size_t row = (((size_t)b * TT) + kt * 64 + tok) * NKV + hk;
            const float4 kq = *(const float4*)(k + row * HD + c4);
            const float4 vq = *(const float4*)(v + row * HD + c4);
            const int dk = bpack_idx(tok, c4);
            kf[dk + 0]  = tf(kq.x);
            kf[dk + 4]  = tf(kq.y);
            kf[dk + 8]  = tf(kq.z);
            kf[dk + 12] = tf(kq.w);
            const int dv = bpack_idx(c4, tok);
            vf[dv + 0]  = tf(vq.x);
            vf[dv + 16] = tf(vq.y);
            vf[dv + 32] = tf(vq.z);
            vf[dv + 48] = tf(vq.w);
        }
        __syncthreads();

        const bool diag = (kt >= 2 * qt);

        // ---- S = Q K^T, softmax, P -> smem
#pragma unroll
        for (int mt = 0; mt < 2; mt++) {
            float sacc[8][4];
#pragma unroll
            for (int nt = 0; nt < 8; nt++)
#pragma unroll
                for (int r = 0; r < 4; r++) sacc[nt][r] = 0.f;

#pragma unroll
            for (int k8 = 0; k8 < 8; k8++)
#pragma unroll
                for (int ntp = 0; ntp < 4; ntp++) {
                    const float4 bf = *(const float4*)(kf + (((ntp * 8 + k8) * 32 + lane) << 2));
                    mma_tf32(sacc[2 * ntp],     qa[mt][k8], __float_as_uint(bf.x), __float_as_uint(bf.y));
                    mma_tf32(sacc[2 * ntp + 1], qa[mt][k8], __float_as_uint(bf.z), __float_as_uint(bf.w));
                }

            const int r0g = qt * 128 + (2 * w + mt) * 16 + lr;   // global q row (half 0)
            if (diag) {
#pragma unroll
                for (int nt = 0; nt < 8; nt++) {
                    const int cg = kt * 64 + nt * 8 + 2 * lc;
                    if (cg     > r0g)     sacc[nt][0] = -INFINITY;
                    if (cg + 1 > r0g)     sacc[nt][1] = -INFINITY;
                    if (cg     > r0g + 8) sacc[nt][2] = -INFINITY;
                    if (cg + 1 > r0g + 8) sacc[nt][3] = -INFINITY;
                }
            }

            float tmax0 = -INFINITY, tmax1 = -INFINITY;
#pragma unroll
            for (int nt = 0; nt < 8; nt++) {
                tmax0 = fmaxf(tmax0, fmaxf(sacc[nt][0], sacc[nt][1]));
                tmax1 = fmaxf(tmax1, fmaxf(sacc[nt][2], sacc[nt][3]));
            }
            tmax0 = fmaxf(tmax0, __shfl_xor_sync(0xffffffffu, tmax0, 1));
            tmax0 = fmaxf(tmax0, __shfl_xor_sync(0xffffffffu, tmax0, 2));
            tmax1 = fmaxf(tmax1, __shfl_xor_sync(0xffffffffu, tmax1, 1));
            tmax1 = fmaxf(tmax1, __shfl_xor_sync(0xffffffffu, tmax1, 2));

            const float mn0 = fmaxf(m[mt][0], tmax0);
            const float mn1 = fmaxf(m[mt][1], tmax1);
            const float al0 = __expf(m[mt][0] - mn0);
            const float al1 = __expf(m[mt][1] - mn1);
            m[mt][0] = mn0; m[mt][1] = mn1;

            float ps0 = 0.f, ps1 = 0.f;
#pragma unroll
            for (int nt = 0; nt < 8; nt++) {
                sacc[nt][0] = __expf(sacc[nt][0] - mn0);
                sacc[nt][1] = __expf(sacc[nt][1] - mn0);
                sacc[nt][2] = __expf(sacc[nt][2] - mn1);
                sacc[nt][3] = __expf(sacc[nt][3] - mn1);
                ps0 += sacc[nt][0] + sacc[nt][1];
                ps1 += sacc[nt][2] + sacc[nt][3];
            }
            ps0 += __shfl_xor_sync(0xffffffffu, ps0, 1);
            ps0 += __shfl_xor_sync(0xffffffffu, ps0, 2);
            ps1 += __shfl_xor_sync(0xffffffffu, ps1, 1);
            ps1 += __shfl_xor_sync(0xffffffffu, ps1, 2);

            l[mt][0] = l[mt][0] * al0 + ps0;
            l[mt][1] = l[mt][1] * al1 + ps1;
#pragma unroll
            for (int nt = 0; nt < 8; nt++) {
                o[mt][nt][0] *= al0; o[mt][nt][1] *= al0;
                o[mt][nt][2] *= al1; o[mt][nt][3] *= al1;
            }

            // store P (tf32) to pq rows [128][66]
            const int pr0 = (2 * w + mt) * 16 + lr;
            const int pc  = 2 * lc;
#pragma unroll
            for (int nt = 0; nt < 8; nt++) {
                *(float2*)(pq + pr0 * 66 + nt * 8 + pc) =
                    make_float2(tf(sacc[nt][0]), tf(sacc[nt][1]));
                *(float2*)(pq + (pr0 + 8) * 66 + nt * 8 + pc) =
                    make_float2(tf(sacc[nt][2]), tf(sacc[nt][3]));
            }
        }
        __syncwarp();

        // ---- O += P V  (P A-frags from pq, V B-frags from vf)
#pragma unroll
        for (int mt = 0; mt < 2; mt++) {
            const int pr0 = (2 * w + mt) * 16 + lr;
#pragma unroll
            for (int k8 = 0; k8 < 8; k8++) {
                uint32_t pa[4];
                const int c0 = k8 * 8 + lc;
                pa[0] = __float_as_uint(pq[pr0 * 66 + c0]);
                pa[1] = __float_as_uint(pq[(pr0 + 8) * 66 + c0]);
                pa[2] = __float_as_uint(pq[pr0 * 66 + c0 + 4]);
                pa[3] = __float_as_uint(pq[(pr0 + 8) * 66 + c0 + 4]);
#pragma unroll
                for (int ntp = 0; ntp < 4; ntp++) {
                    const float4 bf = *(const float4*)(vf + (((ntp * 8 + k8) * 32 + lane) << 2));
                    mma_tf32(o[mt][2 * ntp],     pa, __float_as_uint(bf.x), __float_as_uint(bf.y));
                    mma_tf32(o[mt][2 * ntp + 1], pa, __float_as_uint(bf.z), __float_as_uint(bf.w));
                }
            }
        }
        __syncthreads();
    }

    // ---- epilogue: y = O / l
#pragma unroll
    for (int mt = 0; mt < 2; mt++) {
        const float inv0 = 1.f / l[mt][0];
        const float inv1 = 1.f / l[mt][1];
        const int rg = qt * 128 + (2 * w + mt) * 16 + lr;
        float* y0 = y + (((size_t)b * TT + rg) * NQH + h) * HD;
        float* y1 = y + (((size_t)b * TT + rg + 8) * NQH + h) * HD;
#pragma unroll
        for (int nt = 0; nt < 8; nt++) {
            const int col = nt * 8 + 2 * lc;
            *(float2*)(y0 + col) = make_float2(o[mt][nt][0] * inv0, o[mt][nt][1] * inv0);
            *(float2*)(y1 + col) = make_float2(o[mt][nt][2] * inv1, o[mt][nt][3] * inv1);
        }
    }
}

// ---------------------------------------------------------------------------
extern "C" void kernel_launch(void* const* d_in, const int* in_sizes, int n_in,
                              void* d_out, int out_size)
{
    const float* x  = (const float*)d_in[0];
    const float* Wq = (const float*)d_in[1];
    const float* bq = (const float*)d_in[2];
    const float* Wk = (const float*)d_in[3];
    const float* bk = (const float*)d_in[4];
    const float* Wv = (const float*)d_in[5];
    const float* bv = (const float*)d_in[6];
    const float* Wo = (const float*)d_in[7];
    const float* bo = (const float*)d_in[8];
    float* out = (float*)d_out;

    float *qp, *kp, *vp, *yp;
    cudaGetSymbolAddress((void**)&qp, g_q);
    cudaGetSymbolAddress((void**)&kp, g_k);
    cudaGetSymbolAddress((void**)&vp, g_v);
    cudaGetSymbolAddress((void**)&yp, g_y);

    cudaFuncSetAttribute(gemm_tc, cudaFuncAttributeMaxDynamicSharedMemorySize, GEMM_SMEM);
    cudaFuncSetAttribute(attn_tc, cudaFuncAttributeMaxDynamicSharedMemorySize, ATTN_SMEM);

    // QKV projections (HMMA tf32)
    gemm_tc<<<dim3(EMB / 128, MTOT / 128), 256, GEMM_SMEM>>>(x, Wq, bq, qp, MTOT, EMB, EMB);
    gemm_tc<<<dim3(KVD / 128, MTOT / 128), 256, GEMM_SMEM>>>(x, Wk, bk, kp, MTOT, KVD, EMB);
    gemm_tc<<<dim3(KVD / 128, MTOT / 128), 256, GEMM_SMEM>>>(x, Wv, bv, vp, MTOT, KVD, EMB);

    // RoPE (q scaled by 1/sqrt(HD))
    {
        long nmax = (long)BB * TT * NQH * 32;
        int blocks = (int)((nmax + 255) / 256);
        rope_kernel<<<dim3(blocks, 2), 256>>>(qp, kp);
    }

    // Causal GQA flash attention (HMMA tf32)
    attn_tc<<<dim3(TT / 128, NQH, BB), 128, ATTN_SMEM>>>(qp, kp, vp, yp);

    // Output projection (HMMA tf32)
    gemm_tc<<<dim3(EMB / 128, MTOT / 128), 256, GEMM_SMEM>>>(yp, Wo, bo, out, MTOT, EMB, EMB);
}

// round 5
// speedup vs baseline: 5.2092x; 1.0380x over previous
#include <cuda_runtime.h>
#include <math.h>
#include <stdint.h>

#define EMB   2048
#define NQH   32
#define NKV   8
#define HD    64
#define BB    2
#define TT    2048
#define KVD   (NKV*HD)   // 512
#define MTOT  (BB*TT)    // 4096

// Scratch (no allocations allowed)
__device__ float g_q[(size_t)BB*TT*EMB];   // [B,T,NQH,HD]
__device__ float g_k[(size_t)BB*TT*KVD];   // [B,T,NKV,HD]
__device__ float g_v[(size_t)BB*TT*KVD];   // [B,T,NKV,HD]
__device__ float g_y[(size_t)BB*TT*EMB];   // [B,T,NQH,HD]

static __device__ __forceinline__ uint32_t f2tf(float f) {
    uint32_t u;
    asm("cvt.rna.tf32.f32 %0, %1;" : "=r"(u) : "f"(f));
    return u;
}
static __device__ __forceinline__ float tf(float f) {
    return __uint_as_float(f2tf(f));
}

static __device__ __forceinline__ void mma_tf32(float c[4], const uint32_t a[4],
                                                uint32_t b0, uint32_t b1) {
    asm volatile(
        "mma.sync.aligned.m16n8k8.row.col.f32.tf32.tf32.f32 "
        "{%0,%1,%2,%3}, {%4,%5,%6,%7}, {%8,%9}, {%0,%1,%2,%3};"
        : "+f"(c[0]), "+f"(c[1]), "+f"(c[2]), "+f"(c[3])
        : "r"(a[0]), "r"(a[1]), "r"(a[2]), "r"(a[3]), "r"(b0), "r"(b1));
}

// ===========================================================================
// HMMA tf32 GEMM: C[m][n] = sum_k A[m][k]*W[n][k] + bias[n]  (as in R3/R4)
// ===========================================================================
#define BK 32
#define STAGE_FLOATS 8192
#define GEMM_SMEM (2 * STAGE_FLOATS * 4)

__global__ __launch_bounds__(256)
void gemm_tc(const float* __restrict__ A, const float* __restrict__ W,
             const float* __restrict__ bias, float* __restrict__ C,
             int M, int N, int K)
{
    extern __shared__ float sm[];
    const int tid = threadIdx.x;
    const int wid = tid >> 5;
    const int lane = tid & 31;
    const int wm = wid >> 2;
    const int wn = wid & 3;
    const int bm = blockIdx.y * 128;
    const int bn = blockIdx.x * 128;

    const int NCH = K / BK;

    float acc[4][4][4];
#pragma unroll
    for (int i = 0; i < 4; i++)
#pragma unroll
        for (int j = 0; j < 4; j++)
#pragma unroll
            for (int r = 0; r < 4; r++) acc[i][j][r] = 0.f;

    int a_dst[4], b_dst[4];
#pragma unroll
    for (int i = 0; i < 4; i++) {
        const int idx = tid + 256 * i;
        const int row = idx >> 3;
        const int c0 = (idx & 7) * 4;
        {
            const int r = row & 15, mtile = row >> 4, k8 = c0 >> 3;
            a_dst[i] = ((mtile * 4 + k8) * 32 + (((r & 7) << 2) | (c0 & 3))) * 4 + (r >> 3)
                     + ((((c0 >> 2) & 1)) << 1);
        }
        {
            const int ntile = row >> 3, k8 = c0 >> 3;
            b_dst[i] = 4096 + ((ntile * 4 + k8) * 32 + (((row & 7) << 2) | (c0 & 3))) * 2
                     + ((c0 >> 2) & 1);
        }
    }

    auto stage = [&](const float4* av, const float4* wv, int s) {
        float* dst = sm + s * STAGE_FLOATS;
#pragma unroll
        for (int i = 0; i < 4; i++) {
            float4 v = av[i];
            dst[a_dst[i] + 0]  = tf(v.x);
            dst[a_dst[i] + 4]  = tf(v.y);
            dst[a_dst[i] + 8]  = tf(v.z);
            dst[a_dst[i] + 12] = tf(v.w);
            float4 w = wv[i];
            dst[b_dst[i] + 0] = tf(w.x);
            dst[b_dst[i] + 2] = tf(w.y);
            dst[b_dst[i] + 4] = tf(w.z);
            dst[b_dst[i] + 6] = tf(w.w);
        }
    };

    auto gload = [&](int ch, float4* av, float4* wv) {
        const int k0 = ch * BK;
#pragma unroll
        for (int i = 0; i < 4; i++) {
            const int idx = tid + 256 * i;
            const int row = idx >> 3;
            const int c0 = (idx & 7) * 4;
            av[i] = *(const float4*)(A + (size_t)(bm + row) * K + k0 + c0);
            wv[i] = *(const float4*)(W + (size_t)(bn + row) * K + k0 + c0);
        }
    };

    float4 av[4], wv[4];
    gload(0, av, wv);
    stage(av, wv, 0);
    __syncthreads();

    for (int c = 0; c < NCH; c++) {
        const int s = c & 1;
        const bool more = (c + 1 < NCH);
        if (more) gload(c + 1, av, wv);

        const float* st = sm + s * STAGE_FLOATS;
#pragma unroll
        for (int k8 = 0; k8 < 4; k8++) {
            uint32_t afr[4][4];
            uint32_t bfr[4][2];
#pragma unroll
            for (int mt = 0; mt < 4; mt++) {
                const int mtile = wm * 4 + mt;
                const float4 f = *(const float4*)(st + ((mtile * 4 + k8) * 32 + lane) * 4);
                afr[mt][0] = __float_as_uint(f.x); afr[mt][1] = __float_as_uint(f.y);
                afr[mt][2] = __float_as_uint(f.z); afr[mt][3] = __float_as_uint(f.w);
            }
#pragma unroll
            for (int nt = 0; nt < 4; nt++) {
                const int ntile = wn * 4 + nt;
                const float2 f = *(const float2*)(st + 4096 + ((ntile * 4 + k8) * 32 + lane) * 2);
                bfr[nt][0] = __float_as_uint(f.x); bfr[nt][1] = __float_as_uint(f.y);
            }
#pragma unroll
            for (int mt = 0; mt < 4; mt++)
#pragma unroll
                for (int nt = 0; nt < 4; nt++)
                    mma_tf32(acc[mt][nt], afr[mt], bfr[nt][0], bfr[nt][1]);
        }

        if (more) stage(av, wv, s ^ 1);
        __syncthreads();
    }

    const int rbase = bm + wm * 64 + (lane >> 2);
    const int cbase = bn + wn * 32 + (lane & 3) * 2;
#pragma unroll
    for (int mt = 0; mt < 4; mt++) {
#pragma unroll
        for (int nt = 0; nt < 4; nt++) {
            const int row = rbase + mt * 16;
            const int col = cbase + nt * 8;
            const float2 bb = *(const float2*)(bias + col);
            float2 o0 = make_float2(acc[mt][nt][0] + bb.x, acc[mt][nt][1] + bb.y);
            float2 o1 = make_float2(acc[mt][nt][2] + bb.x, acc[mt][nt][3] + bb.y);
            *(float2*)(C + (size_t)row * N + col) = o0;
            *(float2*)(C + (size_t)(row + 8) * N + col) = o1;
        }
    }
}

// ---------------------------------------------------------------------------
// RoPE in-place on q (y=0, scaled by 0.125) and k (y=1), v (y=2, round only).
// Writes tf32-pre-rounded values so attention staging needs no cvt.
// ---------------------------------------------------------------------------
__global__ __launch_bounds__(256)
void rope_kernel(float* __restrict__ q, float* __restrict__ k, float* __restrict__ v)
{
    const int which = blockIdx.y;
    float* p = (which == 0) ? q : (which == 1) ? k : v;
    const int H = (which == 0) ? NQH : NKV;
    const long n = (long)BB * TT * H * 32;
    const long i = (long)blockIdx.x * blockDim.x + threadIdx.x;
    if (i >= n) return;

    const int  d    = (int)(i & 31);
    const long rest = i >> 5;
    const int  h    = (int)(rest % H);
    const long bt   = rest / H;
    const int  t    = (int)(bt % TT);

    const size_t base = ((size_t)bt * H + h) * HD;
    if (which == 2) {
        p[base + d]      = tf(p[base + d]);
        p[base + d + 32] = tf(p[base + d + 32]);
        return;
    }

    const float inv = expf(d * (-2.0f / 64.0f) * 9.210340371976184f);
    float s, c;
    sincosf((float)t * inv, &s, &c);

    const float x1 = p[base + d];
    const float x2 = p[base + d + 32];
    const float scale = (which == 0) ? 0.125f : 1.0f;
    p[base + d]      = tf((x1 * c - x2 * s) * scale);
    p[base + d + 32] = tf((x2 * c + x1 * s) * scale);
}

// ===========================================================================
// Tensor-core causal flash attention (tf32 HMMA), GQA-fused.
// CTA = 256 threads (8 warps). m = 256 rows = 4 q-heads (one kv group) x 64
// q-tokens. Key tiles of 64. Warp w: head w>>1, tokens (w&1)*32 + [0,32).
// K/V staged once per tile for all 4 heads; next tile prefetched to regs.
// smem: kf 4096 f, vf 4096 f, pq 16896 f (Q pack scratch, then P rows [256][66]).
// ===========================================================================
#define ATTN_SMEM ((4096 + 4096 + 16896) * 4)

// B-frag pack (paired n-tiles): element (n, k), n,k in [0,64)
static __device__ __forceinline__ int bpack_idx(int n, int k) {
    const int nt = n >> 3, k8 = k >> 3;
    const int ln = ((n & 7) << 2) | (k & 3);
    const int reg = (k >> 2) & 1;
    return (((((nt >> 1) * 8) + k8) * 32 + ln) << 2) + ((nt & 1) << 1) + reg;
}
// A-frag pack: element (r, c), r in [0,256), c in [0,64)
static __device__ __forceinline__ int apack_idx(int r, int c) {
    const int mt = r >> 4, k8 = c >> 3;
    const int ln = ((r & 7) << 2) | (c & 3);
    const int reg = ((r >> 3) & 1) | (((c >> 2) & 1) << 1);
    return (((mt * 8 + k8) * 32 + ln) << 2) + reg;
}

__global__ __launch_bounds__(256, 1)
void attn_tc(const float* __restrict__ q, const float* __restrict__ k,
             const float* __restrict__ v, float* __restrict__ y)
{
    extern __shared__ float smf[];
    float* kf = smf;            // 4096
    float* vf = smf + 4096;     // 4096
    float* pq = smf + 8192;     // 16896 (Q pack, then P [256][66])

    const int qt = (gridDim.x - 1) - blockIdx.x;   // big tiles first
    const int hk = blockIdx.y;
    const int b  = blockIdx.z;

    const int tid  = threadIdx.x;
    const int w    = tid >> 5;
    const int lane = tid & 31;
    const int lr   = lane >> 2;
    const int lc   = lane & 3;

    const int h  = hk * 4 + (w >> 1);      // this warp's q-head
    const int tw = (w & 1) * 32;           // token offset within 64-token q tile

    // ---- prologue: load+pack Q (4 heads x 64 tokens = 256 rows x 64)
#pragma unroll
    for (int i = 0; i < 16; i++) {
        const int idx4 = tid + 256 * i;
        const int r  = idx4 >> 4;           // 0..255
        const int c4 = (idx4 & 15) << 2;
        const int tok  = qt * 64 + (r & 63);
        const int head = hk * 4 + (r >> 6);
        const float4 t = *(const float4*)(q + (((size_t)b * TT + tok) * NQH + head) * HD + c4);
        const int d = apack_idx(r, c4);
        pq[d + 0]  = t.x;
        pq[d + 4]  = t.y;
        pq[d + 8]  = t.z;
        pq[d + 12] = t.w;
    }
    __syncthreads();

    uint32_t qa[2][8][4];
#pragma unroll
    for (int mt = 0; mt < 2; mt++)
#pragma unroll
        for (int k8 = 0; k8 < 8; k8++) {
            const float4 f = *(const float4*)(pq + ((((2 * w + mt) * 8 + k8) * 32 + lane) << 2));
            qa[mt][k8][0] = __float_as_uint(f.x);
            qa[mt][k8][1] = __float_as_uint(f.y);
            qa[mt][k8][2] = __float_as_uint(f.z);
            qa[mt][k8][3] = __float_as_uint(f.w);
        }
    __syncthreads();   // pq now free for P

    float m[2][2], l[2][2];
    float o[2][8][4];
#pragma unroll
    for (int mt = 0; mt < 2; mt++) {
        m[mt][0] = -INFINITY; m[mt][1] = -INFINITY;
        l[mt][0] = 0.f;       l[mt][1] = 0.f;
#pragma unroll
        for (int nt = 0; nt < 8; nt++)
#pragma unroll
            for (int r = 0; r < 4; r++) o[mt][nt][r] = 0.f;
    }

    // ---- K/V prefetch registers (4 float4 each)
    float4 kpre[4], vpre[4];
    auto ldkv = [&](int kt) {
#pragma unroll
        for (int i = 0; i < 4; i++) {
            const int idx4 = tid + 256 * i;
            const int tok = idx4 >> 4;          // 0..63
            const int c4  = (idx4 & 15) << 2;
            const size_t row = (((size_t)b * TT) + kt * 64 + tok) * NKV + hk;
            kpre[i] = *(const float4*)(k + row * HD + c4);
            vpre[i] = *(const float4*)(v + row * HD + c4);
        }
    };
    ldkv(0);

    for (int kt = 0; kt <= qt; kt++) {
        // ---- stage prefetched K/V into fragment-packed smem (no cvt needed)
#pragma unroll
        for (int i = 0; i < 4; i++) {
            const int idx4 = tid + 256 * i;
            const int tok = idx4 >> 4;
            const int c4  = (idx4 & 15) << 2;
            const int dk = bpack_idx(tok, c4);
            kf[dk + 0]  = kpre[i].x;
            kf[dk + 4]  = kpre[i].y;
            kf[dk + 8]  = kpre[i].z;
            kf[dk + 12] = kpre[i].w;
            const int dv = bpack_idx(c4, tok);
            vf[dv + 0]  = vpre[i].x;
            vf[dv + 16] = vpre[i].y;
            vf[dv + 32] = vpre[i].z;
            vf[dv + 48] = vpre[i].w;
        }
        __syncthreads();

        if (kt < qt) ldkv(kt + 1);   // hide next tile's LDG under MMA

        const bool diag = (kt == qt);

        // ---- S = Q K^T, softmax, P -> smem
#pragma unroll
        for (int mt = 0; mt < 2; mt++) {
            float sacc[8][4];
#pragma unroll
            for (int nt = 0; nt < 8; nt++)
#pragma unroll
                for (int r = 0; r < 4; r++) sacc[nt][r] = 0.f;

#pragma unroll
            for (int k8 = 0; k8 < 8; k8++)
#pragma unroll
                for (int ntp = 0; ntp < 4; ntp++) {
                    const float4 bf = *(const float4*)(kf + (((ntp * 8 + k8) * 32 + lane) << 2));
                    mma_tf32(sacc[2 * ntp],     qa[mt][k8], __float_as_uint(bf.x), __float_as_uint(bf.y));
                    mma_tf32(sacc[2 * ntp + 1], qa[mt][k8], __float_as_uint(bf.z), __float_as_uint(bf.w));
                }

            const int tl = tw + mt * 16 + lr;   // local q token (lower row half)
            if (diag) {
#pragma unroll
                for (int nt = 0; nt < 8; nt++) {
                    const int cg = nt * 8 + 2 * lc;
                    if (cg     > tl)     sacc[nt][0] = -INFINITY;
                    if (cg + 1 > tl)     sacc[nt][1] = -INFINITY;
                    if (cg     > tl + 8) sacc[nt][2] = -INFINITY;
                    if (cg + 1 > tl + 8) sacc[nt][3] = -INFINITY;
                }
            }

            float tmax0 = -INFINITY, tmax1 = -INFINITY;
#pragma unroll
            for (int nt = 0; nt < 8; nt++) {
                tmax0 = fmaxf(tmax0, fmaxf(sacc[nt][0], sacc[nt][1]));
                tmax1 = fmaxf(tmax1, fmaxf(sacc[nt][2], sacc[nt][3]));
            }
            tmax0 = fmaxf(tmax0, __shfl_xor_sync(0xffffffffu, tmax0, 1));
            tmax0 = fmaxf(tmax0, __shfl_xor_sync(0xffffffffu, tmax0, 2));
            tmax1 = fmaxf(tmax1, __shfl_xor_sync(0xffffffffu, tmax1, 1));
            tmax1 = fmaxf(tmax1, __shfl_xor_sync(0xffffffffu, tmax1, 2));

            const float mn0 = fmaxf(m[mt][0], tmax0);
            const float mn1 = fmaxf(m[mt][1], tmax1);
            const float al0 = __expf(m[mt][0] - mn0);
            const float al1 = __expf(m[mt][1] - mn1);
            m[mt][0] = mn0; m[mt][1] = mn1;

            float ps0 = 0.f, ps1 = 0.f;
#pragma unroll
            for (int nt = 0; nt < 8; nt++) {
                sacc[nt][0] = __expf(sacc[nt][0] - mn0);
                sacc[nt][1] = __expf(sacc[nt][1] - mn0);
                sacc[nt][2] = __expf(sacc[nt][2] - mn1);
                sacc[nt][3] = __expf(sacc[nt][3] - mn1);
                ps0 += sacc[nt][0] + sacc[nt][1];
                ps1 += sacc[nt][2] + sacc[nt][3];
            }
            ps0 += __shfl_xor_sync(0xffffffffu, ps0, 1);
            ps0 += __shfl_xor_sync(0xffffffffu, ps0, 2);
            ps1 += __shfl_xor_sync(0xffffffffu, ps1, 1);
            ps1 += __shfl_xor_sync(0xffffffffu, ps1, 2);

            l[mt][0] = l[mt][0] * al0 + ps0;
            l[mt][1] = l[mt][1] * al1 + ps1;
#pragma unroll
            for (int nt = 0; nt < 8; nt++) {
                o[mt][nt][0] *= al0; o[mt][nt][1] *= al0;
                o[mt][nt][2] *= al1; o[mt][nt][3] *= al1;
            }

            // store P (tf32) to pq rows [256][66]
            const int pr0 = 32 * w + mt * 16 + lr;
            const int pc  = 2 * lc;
#pragma unroll
            for (int nt = 0; nt < 8; nt++) {
                *(float2*)(pq + pr0 * 66 + nt * 8 + pc) =
                    make_float2(tf(sacc[nt][0]), tf(sacc[nt][1]));
                *(float2*)(pq + (pr0 + 8) * 66 + nt * 8 + pc) =
                    make_float2(tf(sacc[nt][2]), tf(sacc[nt][3]));
            }
        }
        __syncwarp();

        // ---- O += P V
#pragma unroll
        for (int mt = 0; mt < 2; mt++) {
            const int pr0 = 32 * w + mt * 16 + lr;
#pragma unroll
            for (int k8 = 0; k8 < 8; k8++) {
                uint32_t pa[4];
                const int c0 = k8 * 8 + lc;
                pa[0] = __float_as_uint(pq[pr0 * 66 + c0]);
                pa[1] = __float_as_uint(pq[(pr0 + 8) * 66 + c0]);
                pa[2] = __float_as_uint(pq[pr0 * 66 + c0 + 4]);
                pa[3] = __float_as_uint(pq[(pr0 + 8) * 66 + c0 + 4]);
#pragma unroll
                for (int ntp = 0; ntp < 4; ntp++) {
                    const float4 bf = *(const float4*)(vf + (((ntp * 8 + k8) * 32 + lane) << 2));
                    mma_tf32(o[mt][2 * ntp],     pa, __float_as_uint(bf.x), __float_as_uint(bf.y));
                    mma_tf32(o[mt][2 * ntp + 1], pa, __float_as_uint(bf.z), __float_as_uint(bf.w));
                }
            }
        }
        __syncthreads();
    }

    // ---- epilogue: y = O / l
#pragma unroll
    for (int mt = 0; mt < 2; mt++) {
        const float inv0 = 1.f / l[mt][0];
        const float inv1 = 1.f / l[mt][1];
        const int tq = qt * 64 + tw + mt * 16 + lr;
        float* y0 = y + (((size_t)b * TT + tq) * NQH + h) * HD;
        float* y1 = y + (((size_t)b * TT + tq + 8) * NQH + h) * HD;
#pragma unroll
        for (int nt = 0; nt < 8; nt++) {
            const int col = nt * 8 + 2 * lc;
            *(float2*)(y0 + col) = make_float2(o[mt][nt][0] * inv0, o[mt][nt][1] * inv0);
            *(float2*)(y1 + col) = make_float2(o[mt][nt][2] * inv1, o[mt][nt][3] * inv1);
        }
    }
}

// ---------------------------------------------------------------------------
extern "C" void kernel_launch(void* const* d_in, const int* in_sizes, int n_in,
                              void* d_out, int out_size)
{
    const float* x  = (const float*)d_in[0];
    const float* Wq = (const float*)d_in[1];
    const float* bq = (const float*)d_in[2];
    const float* Wk = (const float*)d_in[3];
    const float* bk = (const float*)d_in[4];
    const float* Wv = (const float*)d_in[5];
    const float* bv = (const float*)d_in[6];
    const float* Wo = (const float*)d_in[7];
    const float* bo = (const float*)d_in[8];
    float* out = (float*)d_out;

    float *qp, *kp, *vp, *yp;
    cudaGetSymbolAddress((void**)&qp, g_q);
    cudaGetSymbolAddress((void**)&kp, g_k);
    cudaGetSymbolAddress((void**)&vp, g_v);
    cudaGetSymbolAddress((void**)&yp, g_y);

    cudaFuncSetAttribute(gemm_tc, cudaFuncAttributeMaxDynamicSharedMemorySize, GEMM_SMEM);
    cudaFuncSetAttribute(attn_tc, cudaFuncAttributeMaxDynamicSharedMemorySize, ATTN_SMEM);

    // QKV projections (HMMA tf32)
    gemm_tc<<<dim3(EMB / 128, MTOT / 128), 256, GEMM_SMEM>>>(x, Wq, bq, qp, MTOT, EMB, EMB);
    gemm_tc<<<dim3(KVD / 128, MTOT / 128), 256, GEMM_SMEM>>>(x, Wk, bk, kp, MTOT, KVD, EMB);
    gemm_tc<<<dim3(KVD / 128, MTOT / 128), 256, GEMM_SMEM>>>(x, Wv, bv, vp, MTOT, KVD, EMB);

    // RoPE on q,k (q scaled by 1/sqrt(HD)); v tf32-rounded. All pre-rounded.
    {
        long nmax = (long)BB * TT * NQH * 32;
        int blocks = (int)((nmax + 255) / 256);
        rope_kernel<<<dim3(blocks, 3), 256>>>(qp, kp, vp);
    }

    // Causal GQA flash attention (HMMA tf32, 4 heads per CTA)
    attn_tc<<<dim3(TT / 64, NKV, BB), 256, ATTN_SMEM>>>(qp, kp, vp, yp);

    // Output projection (HMMA tf32)
    gemm_tc<<<dim3(EMB / 128, MTOT / 128), 256, GEMM_SMEM>>>(yp, Wo, bo, out, MTOT, EMB, EMB);
}

// round 6
// speedup vs baseline: 5.3930x; 1.0353x over previous
#include <cuda_runtime.h>
#include <math.h>
#include <stdint.h>

#define EMB   2048
#define NQH   32
#define NKV   8
#define HD    64
#define BB    2
#define TT    2048
#define KVD   (NKV*HD)   // 512
#define MTOT  (BB*TT)    // 4096

// Scratch (no allocations allowed)
__device__ float g_q[(size_t)BB*TT*EMB];   // [B,T,NQH,HD]
__device__ float g_k[(size_t)BB*TT*KVD];   // [B,T,NKV,HD]
__device__ float g_v[(size_t)BB*TT*KVD];   // [B,T,NKV,HD]
__device__ float g_y[(size_t)BB*TT*EMB];   // [B,T,NQH,HD]

static __device__ __forceinline__ uint32_t f2tf(float f) {
    uint32_t u;
    asm("cvt.rna.tf32.f32 %0, %1;" : "=r"(u) : "f"(f));
    return u;
}
static __device__ __forceinline__ float tf(float f) {
    return __uint_as_float(f2tf(f));
}

static __device__ __forceinline__ void mma_tf32(float c[4], const uint32_t a[4],
                                                uint32_t b0, uint32_t b1) {
    asm volatile(
        "mma.sync.aligned.m16n8k8.row.col.f32.tf32.tf32.f32 "
        "{%0,%1,%2,%3}, {%4,%5,%6,%7}, {%8,%9}, {%0,%1,%2,%3};"
        : "+f"(c[0]), "+f"(c[1]), "+f"(c[2]), "+f"(c[3])
        : "r"(a[0]), "r"(a[1]), "r"(a[2]), "r"(a[3]), "r"(b0), "r"(b1));
}

// ===========================================================================
// HMMA tf32 GEMM: C[m][n] = sum_k A[m][k]*W[n][k] + bias[n]  (as in R3-R5)
// ===========================================================================
#define BK 32
#define STAGE_FLOATS 8192
#define GEMM_SMEM (2 * STAGE_FLOATS * 4)

__global__ __launch_bounds__(256)
void gemm_tc(const float* __restrict__ A, const float* __restrict__ W,
             const float* __restrict__ bias, float* __restrict__ C,
             int M, int N, int K)
{
    extern __shared__ float sm[];
    const int tid = threadIdx.x;
    const int wid = tid >> 5;
    const int lane = tid & 31;
    const int wm = wid >> 2;
    const int wn = wid & 3;
    const int bm = blockIdx.y * 128;
    const int bn = blockIdx.x * 128;

    const int NCH = K / BK;

    float acc[4][4][4];
#pragma unroll
    for (int i = 0; i < 4; i++)
#pragma unroll
        for (int j = 0; j < 4; j++)
#pragma unroll
            for (int r = 0; r < 4; r++) acc[i][j][r] = 0.f;

    int a_dst[4], b_dst[4];
#pragma unroll
    for (int i = 0; i < 4; i++) {
        const int idx = tid + 256 * i;
        const int row = idx >> 3;
        const int c0 = (idx & 7) * 4;
        {
            const int r = row & 15, mtile = row >> 4, k8 = c0 >> 3;
            a_dst[i] = ((mtile * 4 + k8) * 32 + (((r & 7) << 2) | (c0 & 3))) * 4 + (r >> 3)
                     + ((((c0 >> 2) & 1)) << 1);
        }
        {
            const int ntile = row >> 3, k8 = c0 >> 3;
            b_dst[i] = 4096 + ((ntile * 4 + k8) * 32 + (((row & 7) << 2) | (c0 & 3))) * 2
                     + ((c0 >> 2) & 1);
        }
    }

    auto stage = [&](const float4* av, const float4* wv, int s) {
        float* dst = sm + s * STAGE_FLOATS;
#pragma unroll
        for (int i = 0; i < 4; i++) {
            float4 v = av[i];
            dst[a_dst[i] + 0]  = tf(v.x);
            dst[a_dst[i] + 4]  = tf(v.y);
            dst[a_dst[i] + 8]  = tf(v.z);
            dst[a_dst[i] + 12] = tf(v.w);
            float4 w = wv[i];
            dst[b_dst[i] + 0] = tf(w.x);
            dst[b_dst[i] + 2] = tf(w.y);
            dst[b_dst[i] + 4] = tf(w.z);
            dst[b_dst[i] + 6] = tf(w.w);
        }
    };

    auto gload = [&](int ch, float4* av, float4* wv) {
        const int k0 = ch * BK;
#pragma unroll
        for (int i = 0; i < 4; i++) {
            const int idx = tid + 256 * i;
            const int row = idx >> 3;
            const int c0 = (idx & 7) * 4;
            av[i] = *(const float4*)(A + (size_t)(bm + row) * K + k0 + c0);
            wv[i] = *(const float4*)(W + (size_t)(bn + row) * K + k0 + c0);
        }
    };

    float4 av[4], wv[4];
    gload(0, av, wv);
    stage(av, wv, 0);
    __syncthreads();

    for (int c = 0; c < NCH; c++) {
        const int s = c & 1;
        const bool more = (c + 1 < NCH);
        if (more) gload(c + 1, av, wv);

        const float* st = sm + s * STAGE_FLOATS;
#pragma unroll
        for (int k8 = 0; k8 < 4; k8++) {
            uint32_t afr[4][4];
            uint32_t bfr[4][2];
#pragma unroll
            for (int mt = 0; mt < 4; mt++) {
                const int mtile = wm * 4 + mt;
                const float4 f = *(const float4*)(st + ((mtile * 4 + k8) * 32 + lane) * 4);
                afr[mt][0] = __float_as_uint(f.x); afr[mt][1] = __float_as_uint(f.y);
                afr[mt][2] = __float_as_uint(f.z); afr[mt][3] = __float_as_uint(f.w);
            }
#pragma unroll
            for (int nt = 0; nt < 4; nt++) {
                const int ntile = wn * 4 + nt;
                const float2 f = *(const float2*)(st + 4096 + ((ntile * 4 + k8) * 32 + lane) * 2);
                bfr[nt][0] = __float_as_uint(f.x); bfr[nt][1] = __float_as_uint(f.y);
            }
#pragma unroll
            for (int mt = 0; mt < 4; mt++)
#pragma unroll
                for (int nt = 0; nt < 4; nt++)
                    mma_tf32(acc[mt][nt], afr[mt], bfr[nt][0], bfr[nt][1]);
        }

        if (more) stage(av, wv, s ^ 1);
        __syncthreads();
    }

    const int rbase = bm + wm * 64 + (lane >> 2);
    const int cbase = bn + wn * 32 + (lane & 3) * 2;
#pragma unroll
    for (int mt = 0; mt < 4; mt++) {
#pragma unroll
        for (int nt = 0; nt < 4; nt++) {
            const int row = rbase + mt * 16;
            const int col = cbase + nt * 8;
            const float2 bb = *(const float2*)(bias + col);
            float2 o0 = make_float2(acc[mt][nt][0] + bb.x, acc[mt][nt][1] + bb.y);
            float2 o1 = make_float2(acc[mt][nt][2] + bb.x, acc[mt][nt][3] + bb.y);
            *(float2*)(C + (size_t)row * N + col) = o0;
            *(float2*)(C + (size_t)(row + 8) * N + col) = o1;
        }
    }
}

// ---------------------------------------------------------------------------
// RoPE in-place on q (y=0, scaled by 0.125), k (y=1), v (y=2, round only).
// Writes tf32-pre-rounded values so attention staging needs no cvt.
// ---------------------------------------------------------------------------
__global__ __launch_bounds__(256)
void rope_kernel(float* __restrict__ q, float* __restrict__ k, float* __restrict__ v)
{
    const int which = blockIdx.y;
    float* p = (which == 0) ? q : (which == 1) ? k : v;
    const int H = (which == 0) ? NQH : NKV;
    const long n = (long)BB * TT * H * 32;
    const long i = (long)blockIdx.x * blockDim.x + threadIdx.x;
    if (i >= n) return;

    const int  d    = (int)(i & 31);
    const long rest = i >> 5;
    const int  h    = (int)(rest % H);
    const long bt   = rest / H;
    const int  t    = (int)(bt % TT);

    const size_t base = ((size_t)bt * H + h) * HD;
    if (which == 2) {
        p[base + d]      = tf(p[base + d]);
        p[base + d + 32] = tf(p[base + d + 32]);
        return;
    }

    const float inv = expf(d * (-2.0f / 64.0f) * 9.210340371976184f);
    float s, c;
    sincosf((float)t * inv, &s, &c);

    const float x1 = p[base + d];
    const float x2 = p[base + d + 32];
    const float scale = (which == 0) ? 0.125f : 1.0f;
    p[base + d]      = tf((x1 * c - x2 * s) * scale);
    p[base + d + 32] = tf((x2 * c + x1 * s) * scale);
}

// ===========================================================================
// Tensor-core causal flash attention (tf32 HMMA), GQA-fused, register-P.
// CTA = 256 threads (8 warps). m = 256 rows = 4 q-heads x 64 q-tokens.
// Key tiles of 64, K/V fragment smem DOUBLE-BUFFERED (one sync per tile).
// P never touches smem: S-accumulator -> A-fragment via quad shuffles.
// smem: kf 2x4096 f, vf 2x4096 f, qs 16384 f (Q pack scratch). 128 KB.
// ===========================================================================
#define ATTN_SMEM ((4 * 4096 + 16384) * 4)   // 131072 B

// B-frag pack (paired n-tiles): element (n, k), n,k in [0,64)
static __device__ __forceinline__ int bpack_idx(int n, int k) {
    const int nt = n >> 3, k8 = k >> 3;
    const int ln = ((n & 7) << 2) | (k & 3);
    const int reg = (k >> 2) & 1;
    return (((((nt >> 1) * 8) + k8) * 32 + ln) << 2) + ((nt & 1) << 1) + reg;
}
// A-frag pack: element (r, c), r in [0,256), c in [0,64)
static __device__ __forceinline__ int apack_idx(int r, int c) {
    const int mt = r >> 4, k8 = c >> 3;
    const int ln = ((r & 7) << 2) | (c & 3);
    const int reg = ((r >> 3) & 1) | (((c >> 2) & 1) << 1);
    return (((mt * 8 + k8) * 32 + ln) << 2) + reg;
}

__global__ __launch_bounds__(256, 1)
void attn_tc(const float* __restrict__ q, const float* __restrict__ k,
             const float* __restrict__ v, float* __restrict__ y)
{
    extern __shared__ float smf[];
    float* kf = smf;             // 2 x 4096
    float* vf = smf + 8192;      // 2 x 4096
    float* qs = smf + 16384;     // 16384 (Q pack scratch)

    const int qt = (gridDim.x - 1) - blockIdx.x;   // big tiles first
    const int hk = blockIdx.y;
    const int b  = blockIdx.z;

    const int tid  = threadIdx.x;
    const int w    = tid >> 5;
    const int lane = tid & 31;
    const int lr   = lane >> 2;
    const int lc   = lane & 3;

    const int h  = hk * 4 + (w >> 1);      // this warp's q-head
    const int tw = (w & 1) * 32;           // token offset within 64-token q tile

    // ---- K/V prefetch registers
    float4 kpre[4], vpre[4];
    auto ldkv = [&](int kt) {
#pragma unroll
        for (int i = 0; i < 4; i++) {
            const int idx4 = tid + 256 * i;
            const int tok = idx4 >> 4;
            const int c4  = (idx4 & 15) << 2;
            const size_t row = (((size_t)b * TT) + kt * 64 + tok) * NKV + hk;
            kpre[i] = *(const float4*)(k + row * HD + c4);
            vpre[i] = *(const float4*)(v + row * HD + c4);
        }
    };
    auto stage_to = [&](int s2) {
        float* kd = kf + s2 * 4096;
        float* vd = vf + s2 * 4096;
#pragma unroll
        for (int i = 0; i < 4; i++) {
            const int idx4 = tid + 256 * i;
            const int tok = idx4 >> 4;
            const int c4  = (idx4 & 15) << 2;
            const int dk = bpack_idx(tok, c4);
            kd[dk + 0]  = kpre[i].x;
            kd[dk + 4]  = kpre[i].y;
            kd[dk + 8]  = kpre[i].z;
            kd[dk + 12] = kpre[i].w;
            const int dv = bpack_idx(c4, tok);
            vd[dv + 0]  = vpre[i].x;
            vd[dv + 16] = vpre[i].y;
            vd[dv + 32] = vpre[i].z;
            vd[dv + 48] = vpre[i].w;
        }
    };

    // ---- prologue: K/V tile 0 + Q pack
    ldkv(0);
#pragma unroll
    for (int i = 0; i < 16; i++) {
        const int idx4 = tid + 256 * i;
        const int r  = idx4 >> 4;           // 0..255
        const int c4 = (idx4 & 15) << 2;
        const int tok  = qt * 64 + (r & 63);
        const int head = hk * 4 + (r >> 6);
        const float4 t = *(const float4*)(q + (((size_t)b * TT + tok) * NQH + head) * HD + c4);
        const int d = apack_idx(r, c4);
        qs[d + 0]  = t.x;
        qs[d + 4]  = t.y;
        qs[d + 8]  = t.z;
        qs[d + 12] = t.w;
    }
    stage_to(0);
    __syncthreads();

    uint32_t qa[2][8][4];
#pragma unroll
    for (int mt = 0; mt < 2; mt++)
#pragma unroll
        for (int k8 = 0; k8 < 8; k8++) {
            const float4 f = *(const float4*)(qs + ((((2 * w + mt) * 8 + k8) * 32 + lane) << 2));
            qa[mt][k8][0] = __float_as_uint(f.x);
            qa[mt][k8][1] = __float_as_uint(f.y);
            qa[mt][k8][2] = __float_as_uint(f.z);
            qa[mt][k8][3] = __float_as_uint(f.w);
        }

    float m[2][2], l[2][2];
    float o[2][8][4];
#pragma unroll
    for (int mt = 0; mt < 2; mt++) {
        m[mt][0] = -INFINITY; m[mt][1] = -INFINITY;
        l[mt][0] = 0.f;       l[mt][1] = 0.f;
#pragma unroll
        for (int nt = 0; nt < 8; nt++)
#pragma unroll
            for (int r = 0; r < 4; r++) o[mt][nt][r] = 0.f;
    }

    const int srcA = (lr << 2) | (lc >> 1);
    const int srcB = srcA + 2;
    const bool oddc = (lc & 1);

    for (int kt = 0; kt <= qt; kt++) {
        const int s = kt & 1;
        const float* kfb = kf + s * 4096;
        const float* vfb = vf + s * 4096;
        const bool more = (kt < qt);
        const bool diag = (kt == qt);

        if (more) ldkv(kt + 1);

#pragma unroll
        for (int mt = 0; mt < 2; mt++) {
            // ---- S = Q K^T
            float sacc[8][4];
#pragma unroll
            for (int nt = 0; nt < 8; nt++)
#pragma unroll
                for (int r = 0; r < 4; r++) sacc[nt][r] = 0.f;

#pragma unroll
            for (int k8 = 0; k8 < 8; k8++)
#pragma unroll
                for (int ntp = 0; ntp < 4; ntp++) {
                    const float4 bf = *(const float4*)(kfb + (((ntp * 8 + k8) * 32 + lane) << 2));
                    mma_tf32(sacc[2 * ntp],     qa[mt][k8], __float_as_uint(bf.x), __float_as_uint(bf.y));
                    mma_tf32(sacc[2 * ntp + 1], qa[mt][k8], __float_as_uint(bf.z), __float_as_uint(bf.w));
                }

            const int tl = tw + mt * 16 + lr;   // local q token (lower row half)
            if (diag) {
#pragma unroll
                for (int nt = 0; nt < 8; nt++) {
                    const int cg = nt * 8 + 2 * lc;
                    if (cg     > tl)     sacc[nt][0] = -INFINITY;
                    if (cg + 1 > tl)     sacc[nt][1] = -INFINITY;
                    if (cg     > tl + 8) sacc[nt][2] = -INFINITY;
                    if (cg + 1 > tl + 8) sacc[nt][3] = -INFINITY;
                }
            }

            // ---- online softmax
            float tmax0 = -INFINITY, tmax1 = -INFINITY;
#pragma unroll
            for (int nt = 0; nt < 8; nt++) {
                tmax0 = fmaxf(tmax0, fmaxf(sacc[nt][0], sacc[nt][1]));
                tmax1 = fmaxf(tmax1, fmaxf(sacc[nt][2], sacc[nt][3]));
            }
            tmax0 = fmaxf(tmax0, __shfl_xor_sync(0xffffffffu, tmax0, 1));
            tmax0 = fmaxf(tmax0, __shfl_xor_sync(0xffffffffu, tmax0, 2));
            tmax1 = fmaxf(tmax1, __shfl_xor_sync(0xffffffffu, tmax1, 1));
            tmax1 = fmaxf(tmax1, __shfl_xor_sync(0xffffffffu, tmax1, 2));

            const float mn0 = fmaxf(m[mt][0], tmax0);
            const float mn1 = fmaxf(m[mt][1], tmax1);
            const float al0 = __expf(m[mt][0] - mn0);
            const float al1 = __expf(m[mt][1] - mn1);
            m[mt][0] = mn0; m[mt][1] = mn1;

            float ps0 = 0.f, ps1 = 0.f;
#pragma unroll
            for (int nt = 0; nt < 8; nt++) {
                sacc[nt][0] = tf(__expf(sacc[nt][0] - mn0));
                sacc[nt][1] = tf(__expf(sacc[nt][1] - mn0));
                sacc[nt][2] = tf(__expf(sacc[nt][2] - mn1));
                sacc[nt][3] = tf(__expf(sacc[nt][3] - mn1));
                ps0 += sacc[nt][0] + sacc[nt][1];
                ps1 += sacc[nt][2] + sacc[nt][3];
            }
            ps0 += __shfl_xor_sync(0xffffffffu, ps0, 1);
            ps0 += __shfl_xor_sync(0xffffffffu, ps0, 2);
            ps1 += __shfl_xor_sync(0xffffffffu, ps1, 1);
            ps1 += __shfl_xor_sync(0xffffffffu, ps1, 2);

            l[mt][0] = l[mt][0] * al0 + ps0;
            l[mt][1] = l[mt][1] * al1 + ps1;
#pragma unroll
            for (int nt = 0; nt < 8; nt++) {
                o[mt][nt][0] *= al0; o[mt][nt][1] *= al0;
                o[mt][nt][2] *= al1; o[mt][nt][3] *= al1;
            }

            // ---- O += P V  (P A-frags built from sacc via quad shuffles)
#pragma unroll
            for (int g = 0; g < 8; g++) {
                const float a0 = __shfl_sync(0xffffffffu, sacc[g][0], srcA);
                const float a1 = __shfl_sync(0xffffffffu, sacc[g][1], srcA);
                const float a2 = __shfl_sync(0xffffffffu, sacc[g][2], srcA);
                const float a3 = __shfl_sync(0xffffffffu, sacc[g][3], srcA);
                const float b0 = __shfl_sync(0xffffffffu, sacc[g][0], srcB);
                const float b1 = __shfl_sync(0xffffffffu, sacc[g][1], srcB);
                const float b2 = __shfl_sync(0xffffffffu, sacc[g][2], srcB);
                const float b3 = __shfl_sync(0xffffffffu, sacc[g][3], srcB);
                uint32_t pa[4];
                pa[0] = __float_as_uint(oddc ? a1 : a0);   // (lr,   lc)
                pa[1] = __float_as_uint(oddc ? a3 : a2);   // (lr+8, lc)
                pa[2] = __float_as_uint(oddc ? b1 : b0);   // (lr,   lc+4)
                pa[3] = __float_as_uint(oddc ? b3 : b2);   // (lr+8, lc+4)
#pragma unroll
                for (int ntp = 0; ntp < 4; ntp++) {
                    const float4 bf = *(const float4*)(vfb + (((ntp * 8 + g) * 32 + lane) << 2));
                    mma_tf32(o[mt][2 * ntp],     pa, __float_as_uint(bf.x), __float_as_uint(bf.y));
                    mma_tf32(o[mt][2 * ntp + 1], pa, __float_as_uint(bf.z), __float_as_uint(bf.w));
                }
            }

            // ---- overlap: stage next K/V tile into the other buffer
            if (mt == 0 && more) stage_to(s ^ 1);
        }
        __syncthreads();
    }

    // ---- epilogue: y = O / l
#pragma unroll
    for (int mt = 0; mt < 2; mt++) {
        const float inv0 = 1.f / l[mt][0];
        const float inv1 = 1.f / l[mt][1];
        const int tq = qt * 64 + tw + mt * 16 + lr;
        float* y0 = y + (((size_t)b * TT + tq) * NQH + h) * HD;
        float* y1 = y + (((size_t)b * TT + tq + 8) * NQH + h) * HD;
#pragma unroll
        for (int nt = 0; nt < 8; nt++) {
            const int col = nt * 8 + 2 * lc;
            *(float2*)(y0 + col) = make_float2(o[mt][nt][0] * inv0, o[mt][nt][1] * inv0);
            *(float2*)(y1 + col) = make_float2(o[mt][nt][2] * inv1, o[mt][nt][3] * inv1);
        }
    }
}

// ---------------------------------------------------------------------------
extern "C" void kernel_launch(void* const* d_in, const int* in_sizes, int n_in,
                              void* d_out, int out_size)
{
    const float* x  = (const float*)d_in[0];
    const float* Wq = (const float*)d_in[1];
    const float* bq = (const float*)d_in[2];
    const float* Wk = (const float*)d_in[3];
    const float* bk = (const float*)d_in[4];
    const float* Wv = (const float*)d_in[5];
    const float* bv = (const float*)d_in[6];
    const float* Wo = (const float*)d_in[7];
    const float* bo = (const float*)d_in[8];
    float* out = (float*)d_out;

    float *qp, *kp, *vp, *yp;
    cudaGetSymbolAddress((void**)&qp, g_q);
    cudaGetSymbolAddress((void**)&kp, g_k);
    cudaGetSymbolAddress((void**)&vp, g_v);
    cudaGetSymbolAddress((void**)&yp, g_y);

    cudaFuncSetAttribute(gemm_tc, cudaFuncAttributeMaxDynamicSharedMemorySize, GEMM_SMEM);
    cudaFuncSetAttribute(attn_tc, cudaFuncAttributeMaxDynamicSharedMemorySize, ATTN_SMEM);

    // QKV projections (HMMA tf32)
    gemm_tc<<<dim3(EMB / 128, MTOT / 128), 256, GEMM_SMEM>>>(x, Wq, bq, qp, MTOT, EMB, EMB);
    gemm_tc<<<dim3(KVD / 128, MTOT / 128), 256, GEMM_SMEM>>>(x, Wk, bk, kp, MTOT, KVD, EMB);
    gemm_tc<<<dim3(KVD / 128, MTOT / 128), 256, GEMM_SMEM>>>(x, Wv, bv, vp, MTOT, KVD, EMB);

    // RoPE on q,k (q scaled by 1/sqrt(HD)); v tf32-rounded. All pre-rounded.
    {
        long nmax = (long)BB * TT * NQH * 32;
        int blocks = (int)((nmax + 255) / 256);
        rope_kernel<<<dim3(blocks, 3), 256>>>(qp, kp, vp);
    }

    // Causal GQA flash attention (HMMA tf32, 4 heads per CTA, register-P)
    attn_tc<<<dim3(TT / 64, NKV, BB), 256, ATTN_SMEM>>>(qp, kp, vp, yp);

    // Output projection (HMMA tf32)
    gemm_tc<<<dim3(EMB / 128, MTOT / 128), 256, GEMM_SMEM>>>(yp, Wo, bo, out, MTOT, EMB, EMB);
}

// round 8
// speedup vs baseline: 9.8269x; 1.8222x over previous
#include <cuda_runtime.h>
#include <cuda_fp16.h>
#include <math.h>
#include <stdint.h>

#define EMB   2048
#define NQH   32
#define NKV   8
#define HD    64
#define BB    2
#define TT    2048
#define KVD   (NKV*HD)   // 512
#define MTOT  (BB*TT)    // 4096

// Scratch (no allocations allowed)
__device__ float  g_q[(size_t)BB*TT*EMB];    // fp32 GEMM outputs
__device__ float  g_k[(size_t)BB*TT*KVD];
__device__ float  g_v[(size_t)BB*TT*KVD];
__device__ float  g_y[(size_t)BB*TT*EMB];
__device__ __half g_qh[(size_t)BB*TT*EMB];   // fp16 RoPE'd attention inputs
__device__ __half g_kh[(size_t)BB*TT*KVD];
__device__ __half g_vh[(size_t)BB*TT*KVD];

static __device__ __forceinline__ uint32_t pack2(float a, float b) {
    __half2 h = __floats2half2_rn(a, b);
    return *(uint32_t*)&h;
}

static __device__ __forceinline__ void mma_f16(float c[4], const uint32_t a[4],
                                               uint32_t b0, uint32_t b1) {
    asm volatile(
        "mma.sync.aligned.m16n8k16.row.col.f32.f16.f16.f32 "
        "{%0,%1,%2,%3}, {%4,%5,%6,%7}, {%8,%9}, {%0,%1,%2,%3};"
        : "+f"(c[0]), "+f"(c[1]), "+f"(c[2]), "+f"(c[3])
        : "r"(a[0]), "r"(a[1]), "r"(a[2]), "r"(a[3]), "r"(b0), "r"(b1));
}

// ===========================================================================
// HMMA fp16 GEMM: C[m][n] = sum_k A[m][k]*W[n][k] + bias[n]
// Tile 128x128, BK=32 (2 k16-groups), fragment-packed fp16 smem, 2-stage.
// 8 warps as 2(m) x 4(n), warp tile 64x32.
// ===========================================================================
#define BK 32
#define STAGE_H2 4096                    // A 2048 + W 2048 half2
#define GEMM_SMEM (2 * STAGE_H2 * 4)     // 32768 B

__global__ __launch_bounds__(256)
void gemm_tc(const float* __restrict__ A, const float* __restrict__ W,
             const float* __restrict__ bias, float* __restrict__ C,
             int M, int N, int K)
{
    extern __shared__ __half2 smh[];
    const int tid = threadIdx.x;
    const int wid = tid >> 5;
    const int lane = tid & 31;
    const int wm = wid >> 2;
    const int wn = wid & 3;
    const int bm = blockIdx.y * 128;
    const int bn = blockIdx.x * 128;

    const int NCH = K / BK;

    float acc[4][4][4];
#pragma unroll
    for (int i = 0; i < 4; i++)
#pragma unroll
        for (int j = 0; j < 4; j++)
#pragma unroll
            for (int r = 0; r < 4; r++) acc[i][j][r] = 0.f;

    // per-thread staging addresses (half2 units)
    int a_dst[4], w_dst[4];
#pragma unroll
    for (int i = 0; i < 4; i++) {
        const int idx = tid + 256 * i;
        const int row = idx >> 3;
        const int c0 = (idx & 7) * 4;
        const int kg = c0 >> 4;
        const int l0 = ((row & 7) << 2) | ((c0 & 7) >> 1);
        {
            const int mt = row >> 4;
            const int reg = (((row & 15) >= 8) ? 1 : 0) + (((c0 & 15) >= 8) ? 2 : 0);
            a_dst[i] = ((mt * 2 + kg) * 32 + l0) * 4 + reg;
        }
        {
            const int nt = row >> 3;
            const int reg = ((c0 & 15) >= 8) ? 1 : 0;
            w_dst[i] = 2048 + ((nt * 2 + kg) * 32 + l0) * 2 + reg;
        }
    }

    auto stage = [&](const float4* av, const float4* wv, int s) {
        __half2* dst = smh + s * STAGE_H2;
#pragma unroll
        for (int i = 0; i < 4; i++) {
            dst[a_dst[i]]     = __floats2half2_rn(av[i].x, av[i].y);
            dst[a_dst[i] + 4] = __floats2half2_rn(av[i].z, av[i].w);
            dst[w_dst[i]]     = __floats2half2_rn(wv[i].x, wv[i].y);
            dst[w_dst[i] + 2] = __floats2half2_rn(wv[i].z, wv[i].w);
        }
    };

    auto gload = [&](int ch, float4* av, float4* wv) {
        const int k0 = ch * BK;
#pragma unroll
        for (int i = 0; i < 4; i++) {
            const int idx = tid + 256 * i;
            const int row = idx >> 3;
            const int c0 = (idx & 7) * 4;
            av[i] = *(const float4*)(A + (size_t)(bm + row) * K + k0 + c0);
            wv[i] = *(const float4*)(W + (size_t)(bn + row) * K + k0 + c0);
        }
    };

    float4 av[4], wv[4];
    gload(0, av, wv);
    stage(av, wv, 0);
    __syncthreads();

    for (int c = 0; c < NCH; c++) {
        const int s = c & 1;
        const bool more = (c + 1 < NCH);
        if (more) gload(c + 1, av, wv);

        const __half2* st = smh + s * STAGE_H2;
#pragma unroll
        for (int kg = 0; kg < 2; kg++) {
            uint32_t afr[4][4];
            uint32_t bfr[4][2];
#pragma unroll
            for (int mt = 0; mt < 4; mt++) {
                const uint4 f = *(const uint4*)(st + (((wm * 4 + mt) * 2 + kg) * 32 + lane) * 4);
                afr[mt][0] = f.x; afr[mt][1] = f.y; afr[mt][2] = f.z; afr[mt][3] = f.w;
            }
#pragma unroll
            for (int nt = 0; nt < 4; nt++) {
                const uint2 g = *(const uint2*)(st + 2048 + (((wn * 4 + nt) * 2 + kg) * 32 + lane) * 2);
                bfr[nt][0] = g.x; bfr[nt][1] = g.y;
            }
#pragma unroll
            for (int mt = 0; mt < 4; mt++)
#pragma unroll
                for (int nt = 0; nt < 4; nt++)
                    mma_f16(acc[mt][nt], afr[mt], bfr[nt][0], bfr[nt][1]);
        }

        if (more) stage(av, wv, s ^ 1);
        __syncthreads();
    }

    const int rbase = bm + wm * 64 + (lane >> 2);
    const int cbase = bn + wn * 32 + (lane & 3) * 2;
#pragma unroll
    for (int mt = 0; mt < 4; mt++) {
#pragma unroll
        for (int nt = 0; nt < 4; nt++) {
            const int row = rbase + mt * 16;
            const int col = cbase + nt * 8;
            const float2 bb = *(const float2*)(bias + col);
            float2 o0 = make_float2(acc[mt][nt][0] + bb.x, acc[mt][nt][1] + bb.y);
            float2 o1 = make_float2(acc[mt][nt][2] + bb.x, acc[mt][nt][3] + bb.y);
            *(float2*)(C + (size_t)row * N + col) = o0;
            *(float2*)(C + (size_t)(row + 8) * N + col) = o1;
        }
    }
}

// ---------------------------------------------------------------------------
// RoPE: reads fp32 q/k/v, writes fp16 buffers (q scaled by 0.125, v converted).
// ---------------------------------------------------------------------------
__global__ __launch_bounds__(256)
void rope_kernel(const float* __restrict__ q, const float* __restrict__ k,
                 const float* __restrict__ v, __half* __restrict__ qh,
                 __half* __restrict__ kh, __half* __restrict__ vh)
{
    const int which = blockIdx.y;
    const float* p = (which == 0) ? q : (which == 1) ? k : v;
    __half* ph = (which == 0) ? qh : (which == 1) ? kh : vh;
    const int H = (which == 0) ? NQH : NKV;
    const long n = (long)BB * TT * H * 32;
    const long i = (long)blockIdx.x * blockDim.x + threadIdx.x;
    if (i >= n) return;

    const int  d    = (int)(i & 31);
    const long rest = i >> 5;
    const int  h    = (int)(rest % H);
    const long bt   = rest / H;
    const int  t    = (int)(bt % TT);

    const size_t base = ((size_t)bt * H + h) * HD;
    if (which == 2) {
        ph[base + d]      = __float2half_rn(p[base + d]);
        ph[base + d + 32] = __float2half_rn(p[base + d + 32]);
        return;
    }

    const float inv = expf(d * (-2.0f / 64.0f) * 9.210340371976184f);
    float s, c;
    sincosf((float)t * inv, &s, &c);

    const float x1 = p[base + d];
    const float x2 = p[base + d + 32];
    const float scale = (which == 0) ? 0.125f : 1.0f;
    ph[base + d]      = __float2half_rn((x1 * c - x2 * s) * scale);
    ph[base + d + 32] = __float2half_rn((x2 * c + x1 * s) * scale);
}

// ===========================================================================
// fp16 tensor-core causal flash attention, GQA-fused, zero-shuffle P.
// CTA = 256 threads (8 warps), m = 256 rows = 4 q-heads x 64 q-tokens.
// Key tiles of 64, m16n8k16 fp16 MMAs, f32 accumulate.
// smem (half2): kf 2x2048, vf 2x2048, qs 8192. Total 64 KB.
// ===========================================================================
#define KV_H2 2048                            // 64 tok x 64 d = 4096 halves
#define ATTN_SMEM ((4 * KV_H2 + 8192) * 4)    // 65536 B

__global__ __launch_bounds__(256, 1)
void attn_tc(const __half* __restrict__ q, const __half* __restrict__ k,
             const __half* __restrict__ v, float* __restrict__ y)
{
    extern __shared__ __half2 smh[];
    __half2* kf = smh;                  // 2 x 2048
    __half2* vf = smh + 2 * KV_H2;      // 2 x 2048
    __half2* qs = smh + 4 * KV_H2;      // 8192

    const int qt = (gridDim.x - 1) - blockIdx.x;   // big tiles first
    const int hk = blockIdx.y;
    const int b  = blockIdx.z;

    const int tid  = threadIdx.x;
    const int w    = tid >> 5;
    const int lane = tid & 31;
    const int lr   = lane >> 2;
    const int lc   = lane & 3;

    const int h  = hk * 4 + (w >> 1);
    const int tw = (w & 1) * 32;

    // ---- K/V prefetch regs (uint2 = 4 halves, d-consecutive)
    uint2 kpre[4], vpre[4];
    auto ldkv = [&](int kt) {
#pragma unroll
        for (int i = 0; i < 4; i++) {
            const int idx = tid + 256 * i;
            const int tok = idx >> 4;
            const int d0  = (idx & 15) * 4;
            const size_t off = ((((size_t)b * TT) + kt * 64 + tok) * NKV + hk) * HD + d0;
            kpre[i] = *(const uint2*)(k + off);
            vpre[i] = *(const uint2*)(v + off);
        }
    };
    auto stage_to = [&](int s2) {
        __half2* kd = kf + s2 * KV_H2;
        __half*  vd = (__half*)(vf + s2 * KV_H2);
#pragma unroll
        for (int i = 0; i < 4; i++) {
            const int idx = tid + 256 * i;
            const int tok = idx >> 4;
            const int d0  = (idx & 15) * 4;
            // K: B-frag of S-mma. nt=tok>>3, kg=d0>>4, reg=((d0&15)>=8)
            {
                const int nt = tok >> 3, kg = d0 >> 4;
                const int reg = ((d0 & 15) >= 8) ? 1 : 0;
                const int l0 = ((tok & 7) << 2) | ((d0 & 7) >> 1);
                const int a = ((nt * 4 + kg) * 32 + l0) * 2 + reg;
                kd[a]     = *(const __half2*)&kpre[i].x;   // d0, d0+1
                kd[a + 2] = *(const __half2*)&kpre[i].y;   // d0+2, d0+3
            }
            // V: B-frag of PV-mma. per-half scatter.
            {
                const int kg = tok >> 4;
                const int reg = ((tok & 15) >= 8) ? 1 : 0;
                const int tl = (tok & 7) >> 1;
                const int sel = tok & 1;
                const __half* vh4 = (const __half*)&vpre[i];
#pragma unroll
                for (int j = 0; j < 4; j++) {
                    const int d = d0 + j;
                    const int nt = d >> 3;
                    const int ln = ((d & 7) << 2) | tl;
                    vd[(((nt * 4 + kg) * 32 + ln) * 2 + reg) * 2 + sel] = vh4[j];
                }
            }
        }
    };

    // ---- prologue: K/V tile 0 + Q pack (fp16 A-fragments)
    ldkv(0);
#pragma unroll
    for (int i = 0; i < 8; i++) {
        const int idx = tid + 256 * i;
        const int r  = idx >> 3;            // 0..255
        const int d0 = (idx & 7) * 8;
        const int tok  = qt * 64 + (r & 63);
        const int head = hk * 4 + (r >> 6);
        const uint4 t = *(const uint4*)(q + (((size_t)b * TT + tok) * NQH + head) * HD + d0);
        const int mt = r >> 4, kg = d0 >> 4;
        const int reg = (((r & 15) >= 8) ? 1 : 0) + (((d0 & 15) >= 8) ? 2 : 0);
        const int l0 = (r & 7) << 2;        // (d0&7)>>1 == 0 (d0 multiple of 8)
        const int base = ((mt * 4 + kg) * 32 + l0) * 4 + reg;
        qs[base]      = *(const __half2*)&t.x;
        qs[base + 4]  = *(const __half2*)&t.y;
        qs[base + 8]  = *(const __half2*)&t.z;
        qs[base + 12] = *(const __half2*)&t.w;
    }
    stage_to(0);
    __syncthreads();

    uint32_t qa[2][4][4];
#pragma unroll
    for (int mt = 0; mt < 2; mt++)
#pragma unroll
        for (int kg = 0; kg < 4; kg++) {
            const uint4 f = *(const uint4*)(qs + (((2 * w + mt) * 4 + kg) * 32 + lane) * 4);
            qa[mt][kg][0] = f.x; qa[mt][kg][1] = f.y;
            qa[mt][kg][2] = f.z; qa[mt][kg][3] = f.w;
        }

    float m[2][2], l[2][2];
    float o[2][8][4];
#pragma unroll
    for (int mt = 0; mt < 2; mt++) {
        m[mt][0] = -INFINITY; m[mt][1] = -INFINITY;
        l[mt][0] = 0.f;       l[mt][1] = 0.f;
#pragma unroll
        for (int nt = 0; nt < 8; nt++)
#pragma unroll
            for (int r = 0; r < 4; r++) o[mt][nt][r] = 0.f;
    }

    for (int kt = 0; kt <= qt; kt++) {
        const int s = kt & 1;
        const __half2* kfb = kf + s * KV_H2;
        const __half2* vfb = vf + s * KV_H2;
        const bool more = (kt < qt);
        const bool diag = (kt == qt);

        if (more) ldkv(kt + 1);

#pragma unroll
        for (int mt = 0; mt < 2; mt++) {
            // ---- S = Q K^T (fp16, f32 accum)
            float sacc[8][4];
#pragma unroll
            for (int nt = 0; nt < 8; nt++)
#pragma unroll
                for (int r = 0; r < 4; r++) sacc[nt][r] = 0.f;

#pragma unroll
            for (int kg = 0; kg < 4; kg++)
#pragma unroll
                for (int nt = 0; nt < 8; nt++) {
                    const uint2 bb = *(const uint2*)(kfb + ((nt * 4 + kg) * 32 + lane) * 2);
                    mma_f16(sacc[nt], qa[mt][kg], bb.x, bb.y);
                }

            const int tl = tw + mt * 16 + lr;
            if (diag) {
#pragma unroll
                for (int nt = 0; nt < 8; nt++) {
                    const int cg = nt * 8 + 2 * lc;
                    if (cg     > tl)     sacc[nt][0] = -INFINITY;
                    if (cg + 1 > tl)     sacc[nt][1] = -INFINITY;
                    if (cg     > tl + 8) sacc[nt][2] = -INFINITY;
                    if (cg + 1 > tl + 8) sacc[nt][3] = -INFINITY;
                }
            }

            // ---- online softmax
            float tmax0 = -INFINITY, tmax1 = -INFINITY;
#pragma unroll
            for (int nt = 0; nt < 8; nt++) {
                tmax0 = fmaxf(tmax0, fmaxf(sacc[nt][0], sacc[nt][1]));
                tmax1 = fmaxf(tmax1, fmaxf(sacc[nt][2], sacc[nt][3]));
            }
            tmax0 = fmaxf(tmax0, __shfl_xor_sync(0xffffffffu, tmax0, 1));
            tmax0 = fmaxf(tmax0, __shfl_xor_sync(0xffffffffu, tmax0, 2));
            tmax1 = fmaxf(tmax1, __shfl_xor_sync(0xffffffffu, tmax1, 1));
            tmax1 = fmaxf(tmax1, __shfl_xor_sync(0xffffffffu, tmax1, 2));

            const float mn0 = fmaxf(m[mt][0], tmax0);
            const float mn1 = fmaxf(m[mt][1], tmax1);
            const float al0 = __expf(m[mt][0] - mn0);
            const float al1 = __expf(m[mt][1] - mn1);
            m[mt][0] = mn0; m[mt][1] = mn1;

            float ps0 = 0.f, ps1 = 0.f;
#pragma unroll
            for (int nt = 0; nt < 8; nt++) {
                sacc[nt][0] = __expf(sacc[nt][0] - mn0);
                sacc[nt][1] = __expf(sacc[nt][1] - mn0);
                sacc[nt][2] = __expf(sacc[nt][2] - mn1);
                sacc[nt][3] = __expf(sacc[nt][3] - mn1);
                ps0 += sacc[nt][0] + sacc[nt][1];
                ps1 += sacc[nt][2] + sacc[nt][3];
            }
            ps0 += __shfl_xor_sync(0xffffffffu, ps0, 1);
            ps0 += __shfl_xor_sync(0xffffffffu, ps0, 2);
            ps1 += __shfl_xor_sync(0xffffffffu, ps1, 1);
            ps1 += __shfl_xor_sync(0xffffffffu, ps1, 2);

            l[mt][0] = l[mt][0] * al0 + ps0;
            l[mt][1] = l[mt][1] * al1 + ps1;
#pragma unroll
            for (int nt = 0; nt < 8; nt++) {
                o[mt][nt][0] *= al0; o[mt][nt][1] *= al0;
                o[mt][nt][2] *= al1; o[mt][nt][3] *= al1;
            }

            // ---- O += P V : P A-frag = accumulator layout, zero shuffles
#pragma unroll
            for (int kg = 0; kg < 4; kg++) {
                uint32_t pa[4];
                pa[0] = pack2(sacc[2 * kg][0],     sacc[2 * kg][1]);
                pa[1] = pack2(sacc[2 * kg][2],     sacc[2 * kg][3]);
                pa[2] = pack2(sacc[2 * kg + 1][0], sacc[2 * kg + 1][1]);
                pa[3] = pack2(sacc[2 * kg + 1][2], sacc[2 * kg + 1][3]);
#pragma unroll
                for (int nt = 0; nt < 8; nt++) {
                    const uint2 bb = *(const uint2*)(vfb + ((nt * 4 + kg) * 32 + lane) * 2);
                    mma_f16(o[mt][nt], pa, bb.x, bb.y);
                }
            }

            if (mt == 0 && more) stage_to(s ^ 1);
        }
        __syncthreads();
    }

    // ---- epilogue: y = O / l
#pragma unroll
    for (int mt = 0; mt < 2; mt++) {
        const float inv0 = 1.f / l[mt][0];
        const float inv1 = 1.f / l[mt][1];
        const int tq = qt * 64 + tw + mt * 16 + lr;
        float* y0 = y + (((size_t)b * TT + tq) * NQH + h) * HD;
        float* y1 = y + (((size_t)b * TT + tq + 8) * NQH + h) * HD;
#pragma unroll
        for (int nt = 0; nt < 8; nt++) {
            const int col = nt * 8 + 2 * lc;
            *(float2*)(y0 + col) = make_float2(o[mt][nt][0] * inv0, o[mt][nt][1] * inv0);
            *(float2*)(y1 + col) = make_float2(o[mt][nt][2] * inv1, o[mt][nt][3] * inv1);
        }
    }
}

// ---------------------------------------------------------------------------
extern "C" void kernel_launch(void* const* d_in, const int* in_sizes, int n_in,
                              void* d_out, int out_size)
{
    const float* x  = (const float*)d_in[0];
    const float* Wq = (const float*)d_in[1];
    const float* bq = (const float*)d_in[2];
    const float* Wk = (const float*)d_in[3];
    const float* bk = (const float*)d_in[4];
    const float* Wv = (const float*)d_in[5];
    const float* bv = (const float*)d_in[6];
    const float* Wo = (const float*)d_in[7];
    const float* bo = (const float*)d_in[8];
    float* out = (float*)d_out;

    float *qp, *kp, *vp, *yp;
    __half *qh, *kh, *vh;
    cudaGetSymbolAddress((void**)&qp, g_q);
    cudaGetSymbolAddress((void**)&kp, g_k);
    cudaGetSymbolAddress((void**)&vp, g_v);
    cudaGetSymbolAddress((void**)&yp, g_y);
    cudaGetSymbolAddress((void**)&qh, g_qh);
    cudaGetSymbolAddress((void**)&kh, g_kh);
    cudaGetSymbolAddress((void**)&vh, g_vh);

    cudaFuncSetAttribute(gemm_tc, cudaFuncAttributeMaxDynamicSharedMemorySize, GEMM_SMEM);
    cudaFuncSetAttribute(attn_tc, cudaFuncAttributeMaxDynamicSharedMemorySize, ATTN_SMEM);

    // QKV projections (HMMA fp16, f32 accumulate)
    gemm_tc<<<dim3(EMB / 128, MTOT / 128), 256, GEMM_SMEM>>>(x, Wq, bq, qp, MTOT, EMB, EMB);
    gemm_tc<<<dim3(KVD / 128, MTOT / 128), 256, GEMM_SMEM>>>(x, Wk, bk, kp, MTOT, KVD, EMB);
    gemm_tc<<<dim3(KVD / 128, MTOT / 128), 256, GEMM_SMEM>>>(x, Wv, bv, vp, MTOT, KVD, EMB);

    // RoPE: q scaled by 1/sqrt(HD); outputs fp16 buffers
    {
        long nmax = (long)BB * TT * NQH * 32;
        int blocks = (int)((nmax + 255) / 256);
        rope_kernel<<<dim3(blocks, 3), 256>>>(qp, kp, vp, qh, kh, vh);
    }

    // Causal GQA flash attention (fp16 HMMA, 4 heads per CTA)
    attn_tc<<<dim3(TT / 64, NKV, BB), 256, ATTN_SMEM>>>(qh, kh, vh, yp);

    // Output projection (HMMA fp16)
    gemm_tc<<<dim3(EMB / 128, MTOT / 128), 256, GEMM_SMEM>>>(yp, Wo, bo, out, MTOT, EMB, EMB);
}

// round 9
// speedup vs baseline: 11.0182x; 1.1212x over previous
#include <cuda_runtime.h>
#include <cuda_fp16.h>
#include <math.h>
#include <stdint.h>

#define EMB   2048
#define NQH   32
#define NKV   8
#define HD    64
#define BB    2
#define TT    2048
#define KVD   (NKV*HD)   // 512
#define MTOT  (BB*TT)    // 4096

// Scratch (no allocations allowed)
__device__ float  g_q[(size_t)BB*TT*EMB];    // fp32 GEMM outputs
__device__ float  g_k[(size_t)BB*TT*KVD];
__device__ float  g_v[(size_t)BB*TT*KVD];
__device__ float  g_y[(size_t)BB*TT*EMB];
__device__ __half g_qh[(size_t)BB*TT*EMB];   // fp16 RoPE'd q (pre-scaled by 0.125*log2e)
__device__ __half g_kh[(size_t)BB*TT*KVD];   // fp16 RoPE'd k
__device__ __half g_vth[(size_t)BB*NKV*HD*TT]; // fp16 V transposed: [b][hk][d][t]

static __device__ __forceinline__ uint32_t pack2(float a, float b) {
    __half2 h = __floats2half2_rn(a, b);
    return *(uint32_t*)&h;
}
static __device__ __forceinline__ float ex2(float x) {
    float r; asm("ex2.approx.f32 %0, %1;" : "=f"(r) : "f"(x)); return r;
}

static __device__ __forceinline__ void mma_f16(float c[4], const uint32_t a[4],
                                               uint32_t b0, uint32_t b1) {
    asm volatile(
        "mma.sync.aligned.m16n8k16.row.col.f32.f16.f16.f32 "
        "{%0,%1,%2,%3}, {%4,%5,%6,%7}, {%8,%9}, {%0,%1,%2,%3};"
        : "+f"(c[0]), "+f"(c[1]), "+f"(c[2]), "+f"(c[3])
        : "r"(a[0]), "r"(a[1]), "r"(a[2]), "r"(a[3]), "r"(b0), "r"(b1));
}

// ===========================================================================
// HMMA fp16 GEMM (unchanged from R8): C[m][n] = sum_k A[m][k]*W[n][k] + bias[n]
// ===========================================================================
#define BK 32
#define STAGE_H2 4096
#define GEMM_SMEM (2 * STAGE_H2 * 4)

__global__ __launch_bounds__(256)
void gemm_tc(const float* __restrict__ A, const float* __restrict__ W,
             const float* __restrict__ bias, float* __restrict__ C,
             int M, int N, int K)
{
    extern __shared__ __half2 smh[];
    const int tid = threadIdx.x;
    const int wid = tid >> 5;
    const int lane = tid & 31;
    const int wm = wid >> 2;
    const int wn = wid & 3;
    const int bm = blockIdx.y * 128;
    const int bn = blockIdx.x * 128;

    const int NCH = K / BK;

    float acc[4][4][4];
#pragma unroll
    for (int i = 0; i < 4; i++)
#pragma unroll
        for (int j = 0; j < 4; j++)
#pragma unroll
            for (int r = 0; r < 4; r++) acc[i][j][r] = 0.f;

    int a_dst[4], w_dst[4];
#pragma unroll
    for (int i = 0; i < 4; i++) {
        const int idx = tid + 256 * i;
        const int row = idx >> 3;
        const int c0 = (idx & 7) * 4;
        const int kg = c0 >> 4;
        const int l0 = ((row & 7) << 2) | ((c0 & 7) >> 1);
        {
            const int mt = row >> 4;
            const int reg = (((row & 15) >= 8) ? 1 : 0) + (((c0 & 15) >= 8) ? 2 : 0);
            a_dst[i] = ((mt * 2 + kg) * 32 + l0) * 4 + reg;
        }
        {
            const int nt = row >> 3;
            const int reg = ((c0 & 15) >= 8) ? 1 : 0;
            w_dst[i] = 2048 + ((nt * 2 + kg) * 32 + l0) * 2 + reg;
        }
    }

    auto stage = [&](const float4* av, const float4* wv, int s) {
        __half2* dst = smh + s * STAGE_H2;
#pragma unroll
        for (int i = 0; i < 4; i++) {
            dst[a_dst[i]]     = __floats2half2_rn(av[i].x, av[i].y);
            dst[a_dst[i] + 4] = __floats2half2_rn(av[i].z, av[i].w);
            dst[w_dst[i]]     = __floats2half2_rn(wv[i].x, wv[i].y);
            dst[w_dst[i] + 2] = __floats2half2_rn(wv[i].z, wv[i].w);
        }
    };

    auto gload = [&](int ch, float4* av, float4* wv) {
        const int k0 = ch * BK;
#pragma unroll
        for (int i = 0; i < 4; i++) {
            const int idx = tid + 256 * i;
            const int row = idx >> 3;
            const int c0 = (idx & 7) * 4;
            av[i] = *(const float4*)(A + (size_t)(bm + row) * K + k0 + c0);
            wv[i] = *(const float4*)(W + (size_t)(bn + row) * K + k0 + c0);
        }
    };

    float4 av[4], wv[4];
    gload(0, av, wv);
    stage(av, wv, 0);
    __syncthreads();

    for (int c = 0; c < NCH; c++) {
        const int s = c & 1;
        const bool more = (c + 1 < NCH);
        if (more) gload(c + 1, av, wv);

        const __half2* st = smh + s * STAGE_H2;
#pragma unroll
        for (int kg = 0; kg < 2; kg++) {
            uint32_t afr[4][4];
            uint32_t bfr[4][2];
#pragma unroll
            for (int mt = 0; mt < 4; mt++) {
                const uint4 f = *(const uint4*)(st + (((wm * 4 + mt) * 2 + kg) * 32 + lane) * 4);
                afr[mt][0] = f.x; afr[mt][1] = f.y; afr[mt][2] = f.z; afr[mt][3] = f.w;
            }
#pragma unroll
            for (int nt = 0; nt < 4; nt++) {
                const uint2 g = *(const uint2*)(st + 2048 + (((wn * 4 + nt) * 2 + kg) * 32 + lane) * 2);
                bfr[nt][0] = g.x; bfr[nt][1] = g.y;
            }
#pragma unroll
            for (int mt = 0; mt < 4; mt++)
#pragma unroll
                for (int nt = 0; nt < 4; nt++)
                    mma_f16(acc[mt][nt], afr[mt], bfr[nt][0], bfr[nt][1]);
        }

        if (more) stage(av, wv, s ^ 1);
        __syncthreads();
    }

    const int rbase = bm + wm * 64 + (lane >> 2);
    const int cbase = bn + wn * 32 + (lane & 3) * 2;
#pragma unroll
    for (int mt = 0; mt < 4; mt++) {
#pragma unroll
        for (int nt = 0; nt < 4; nt++) {
            const int row = rbase + mt * 16;
            const int col = cbase + nt * 8;
            const float2 bb = *(const float2*)(bias + col);
            float2 o0 = make_float2(acc[mt][nt][0] + bb.x, acc[mt][nt][1] + bb.y);
            float2 o1 = make_float2(acc[mt][nt][2] + bb.x, acc[mt][nt][3] + bb.y);
            *(float2*)(C + (size_t)row * N + col) = o0;
            *(float2*)(C + (size_t)(row + 8) * N + col) = o1;
        }
    }
}

// ---------------------------------------------------------------------------
// RoPE: reads fp32 q/k, writes fp16 (q scaled by 0.125*log2e for base-2 softmax)
// ---------------------------------------------------------------------------
#define QSCALE 0.18033688011112042f   // 0.125 * log2(e)

__global__ __launch_bounds__(256)
void rope_kernel(const float* __restrict__ q, const float* __restrict__ k,
                 __half* __restrict__ qh, __half* __restrict__ kh)
{
    const int which = blockIdx.y;
    const float* p = (which == 0) ? q : k;
    __half* ph = (which == 0) ? qh : kh;
    const int H = (which == 0) ? NQH : NKV;
    const long n = (long)BB * TT * H * 32;
    const long i = (long)blockIdx.x * blockDim.x + threadIdx.x;
    if (i >= n) return;

    const int  d    = (int)(i & 31);
    const long rest = i >> 5;
    const int  h    = (int)(rest % H);
    const long bt   = rest / H;
    const int  t    = (int)(bt % TT);

    const float inv = expf(d * (-2.0f / 64.0f) * 9.210340371976184f);
    float s, c;
    sincosf((float)t * inv, &s, &c);

    const size_t base = ((size_t)bt * H + h) * HD;
    const float x1 = p[base + d];
    const float x2 = p[base + d + 32];
    const float scale = (which == 0) ? QSCALE : 1.0f;
    ph[base + d]      = __float2half_rn((x1 * c - x2 * s) * scale);
    ph[base + d + 32] = __float2half_rn((x2 * c + x1 * s) * scale);
}

// ---------------------------------------------------------------------------
// V transpose: fp32 v [b][t][hk][d] -> fp16 vT [b][hk][d][t]
// grid (TT/32, NKV, BB), 256 threads, smem tile 64d x 32t.
// ---------------------------------------------------------------------------
__global__ __launch_bounds__(256)
void vt_kernel(const float* __restrict__ v, __half* __restrict__ vt)
{
    __shared__ float tile[64][33];
    const int t0 = blockIdx.x * 32;
    const int hk = blockIdx.y;
    const int b  = blockIdx.z;
    const int tid = threadIdx.x;
#pragma unroll
    for (int i = 0; i < 8; i++) {
        const int idx = tid + 256 * i;
        const int tl = idx >> 6;        // 0..31
        const int d  = idx & 63;
        tile[d][tl] = v[(((size_t)b * TT + t0 + tl) * NKV + hk) * HD + d];
    }
    __syncthreads();
#pragma unroll
    for (int i = 0; i < 8; i++) {
        const int idx = tid + 256 * i;
        const int d  = idx >> 5;        // 0..63
        const int tl = idx & 31;
        vt[(((size_t)b * NKV + hk) * HD + d) * TT + t0 + tl] = __float2half_rn(tile[d][tl]);
    }
}

// ===========================================================================
// fp16 tensor-core causal flash attention, GQA-fused, zero-shuffle P,
// base-2 softmax, V pre-transposed (V staging == K staging pattern).
// CTA = 256 threads (8 warps), m = 256 rows = 4 q-heads x 64 q-tokens.
// smem (half2): kf 2x2048, vf 2x2048, qs 8192. Total 64 KB.
// ===========================================================================
#define KV_H2 2048
#define ATTN_SMEM ((4 * KV_H2 + 8192) * 4)    // 65536 B

__global__ __launch_bounds__(256, 1)
void attn_tc(const __half* __restrict__ q, const __half* __restrict__ k,
             const __half* __restrict__ vt, float* __restrict__ y)
{
    extern __shared__ __half2 smh[];
    __half2* kf = smh;                  // 2 x 2048
    __half2* vf = smh + 2 * KV_H2;      // 2 x 2048
    __half2* qs = smh + 4 * KV_H2;      // 8192

    const int qt = (gridDim.x - 1) - blockIdx.x;   // big tiles first
    const int hk = blockIdx.y;
    const int b  = blockIdx.z;

    const int tid  = threadIdx.x;
    const int w    = tid >> 5;
    const int lane = tid & 31;
    const int lr   = lane >> 2;
    const int lc   = lane & 3;

    const int h  = hk * 4 + (w >> 1);
    const int tw = (w & 1) * 32;

    // ---- K/V^T prefetch regs (uint2 = 4 halves along fastest dim)
    uint2 kpre[4], vpre[4];
    auto ldkv = [&](int kt) {
#pragma unroll
        for (int i = 0; i < 4; i++) {
            const int idx = tid + 256 * i;
            const int r4  = idx >> 4;           // K: token | V^T: d-row
            const int c0  = (idx & 15) * 4;     // K: d     | V^T: token
            kpre[i] = *(const uint2*)(k + ((((size_t)b * TT) + kt * 64 + r4) * NKV + hk) * HD + c0);
            vpre[i] = *(const uint2*)(vt + (((size_t)b * NKV + hk) * HD + r4) * TT + kt * 64 + c0);
        }
    };
    // Identical fragment-pack for K (n=tok,k=d) and V^T (n=d,k=tok)
    auto stage_to = [&](int s2) {
        __half2* kd = kf + s2 * KV_H2;
        __half2* vd = vf + s2 * KV_H2;
#pragma unroll
        for (int i = 0; i < 4; i++) {
            const int idx = tid + 256 * i;
            const int r4 = idx >> 4;
            const int c0 = (idx & 15) * 4;
            const int nt = r4 >> 3, kg = c0 >> 4;
            const int reg = ((c0 & 15) >= 8) ? 1 : 0;
            const int l0 = ((r4 & 7) << 2) | ((c0 & 7) >> 1);
            const int a = ((nt * 4 + kg) * 32 + l0) * 2 + reg;
            kd[a]     = *(const __half2*)&kpre[i].x;
            kd[a + 2] = *(const __half2*)&kpre[i].y;
            vd[a]     = *(const __half2*)&vpre[i].x;
            vd[a + 2] = *(const __half2*)&vpre[i].y;
        }
    };

    // ---- prologue: K/V tile 0 + Q pack (fp16 A-fragments)
    ldkv(0);
#pragma unroll
    for (int i = 0; i < 8; i++) {
        const int idx = tid + 256 * i;
        const int r  = idx >> 3;            // 0..255
        const int d0 = (idx & 7) * 8;
        const int tok  = qt * 64 + (r & 63);
        const int head = hk * 4 + (r >> 6);
        const uint4 t = *(const uint4*)(q + (((size_t)b * TT + tok) * NQH + head) * HD + d0);
        const int mt = r >> 4, kg = d0 >> 4;
        const int reg = (((r & 15) >= 8) ? 1 : 0) + (((d0 & 15) >= 8) ? 2 : 0);
        const int l0 = (r & 7) << 2;
        const int base = ((mt * 4 + kg) * 32 + l0) * 4 + reg;
        qs[base]      = *(const __half2*)&t.x;
        qs[base + 4]  = *(const __half2*)&t.y;
        qs[base + 8]  = *(const __half2*)&t.z;
        qs[base + 12] = *(const __half2*)&t.w;
    }
    stage_to(0);
    __syncthreads();

    uint32_t qa[2][4][4];
#pragma unroll
    for (int mt = 0; mt < 2; mt++)
#pragma unroll
        for (int kg = 0; kg < 4; kg++) {
            const uint4 f = *(const uint4*)(qs + (((2 * w + mt) * 4 + kg) * 32 + lane) * 4);
            qa[mt][kg][0] = f.x; qa[mt][kg][1] = f.y;
            qa[mt][kg][2] = f.z; qa[mt][kg][3] = f.w;
        }

    float m[2][2], l[2][2];
    float o[2][8][4];
#pragma unroll
    for (int mt = 0; mt < 2; mt++) {
        m[mt][0] = -INFINITY; m[mt][1] = -INFINITY;
        l[mt][0] = 0.f;       l[mt][1] = 0.f;
#pragma unroll
        for (int nt = 0; nt < 8; nt++)
#pragma unroll
            for (int r = 0; r < 4; r++) o[mt][nt][r] = 0.f;
    }

    for (int kt = 0; kt <= qt; kt++) {
        const int s = kt & 1;
        const __half2* kfb = kf + s * KV_H2;
        const __half2* vfb = vf + s * KV_H2;
        const bool more = (kt < qt);
        const bool diag = (kt == qt);

        if (more) ldkv(kt + 1);

#pragma unroll
        for (int mt = 0; mt < 2; mt++) {
            // ---- S = Q K^T (fp16, f32 accum) — S in base-2 logit units
            float sacc[8][4];
#pragma unroll
            for (int nt = 0; nt < 8; nt++)
#pragma unroll
                for (int r = 0; r < 4; r++) sacc[nt][r] = 0.f;

#pragma unroll
            for (int kg = 0; kg < 4; kg++)
#pragma unroll
                for (int nt = 0; nt < 8; nt++) {
                    const uint2 bb = *(const uint2*)(kfb + ((nt * 4 + kg) * 32 + lane) * 2);
                    mma_f16(sacc[nt], qa[mt][kg], bb.x, bb.y);
                }

            const int tl = tw + mt * 16 + lr;
            if (diag) {
#pragma unroll
                for (int nt = 0; nt < 8; nt++) {
                    const int cg = nt * 8 + 2 * lc;
                    if (cg     > tl)     sacc[nt][0] = -INFINITY;
                    if (cg + 1 > tl)     sacc[nt][1] = -INFINITY;
                    if (cg     > tl + 8) sacc[nt][2] = -INFINITY;
                    if (cg + 1 > tl + 8) sacc[nt][3] = -INFINITY;
                }
            }

            // ---- online softmax (base 2)
            float tmax0 = -INFINITY, tmax1 = -INFINITY;
#pragma unroll
            for (int nt = 0; nt < 8; nt++) {
                tmax0 = fmaxf(tmax0, fmaxf(sacc[nt][0], sacc[nt][1]));
                tmax1 = fmaxf(tmax1, fmaxf(sacc[nt][2], sacc[nt][3]));
            }
            tmax0 = fmaxf(tmax0, __shfl_xor_sync(0xffffffffu, tmax0, 1));
            tmax0 = fmaxf(tmax0, __shfl_xor_sync(0xffffffffu, tmax0, 2));
            tmax1 = fmaxf(tmax1, __shfl_xor_sync(0xffffffffu, tmax1, 1));
            tmax1 = fmaxf(tmax1, __shfl_xor_sync(0xffffffffu, tmax1, 2));

            const float mn0 = fmaxf(m[mt][0], tmax0);
            const float mn1 = fmaxf(m[mt][1], tmax1);
            const float al0 = ex2(m[mt][0] - mn0);
            const float al1 = ex2(m[mt][1] - mn1);
            m[mt][0] = mn0; m[mt][1] = mn1;

            float ps0 = 0.f, ps1 = 0.f;
#pragma unroll
            for (int nt = 0; nt < 8; nt++) {
                sacc[nt][0] = ex2(sacc[nt][0] - mn0);
                sacc[nt][1] = ex2(sacc[nt][1] - mn0);
                sacc[nt][2] = ex2(sacc[nt][2] - mn1);
                sacc[nt][3] = ex2(sacc[nt][3] - mn1);
                ps0 += sacc[nt][0] + sacc[nt][1];
                ps1 += sacc[nt][2] + sacc[nt][3];
            }
            ps0 += __shfl_xor_sync(0xffffffffu, ps0, 1);
            ps0 += __shfl_xor_sync(0xffffffffu, ps0, 2);
            ps1 += __shfl_xor_sync(0xffffffffu, ps1, 1);
            ps1 += __shfl_xor_sync(0xffffffffu, ps1, 2);

            l[mt][0] = l[mt][0] * al0 + ps0;
            l[mt][1] = l[mt][1] * al1 + ps1;
#pragma unroll
            for (int nt = 0; nt < 8; nt++) {
                o[mt][nt][0] *= al0; o[mt][nt][1] *= al0;
                o[mt][nt][2] *= al1; o[mt][nt][3] *= al1;
            }

            // ---- O += P V : P A-frag = accumulator layout, zero shuffles
#pragma unroll
            for (int kg = 0; kg < 4; kg++) {
                uint32_t pa[4];
                pa[0] = pack2(sacc[2 * kg][0],     sacc[2 * kg][1]);
                pa[1] = pack2(sacc[2 * kg][2],     sacc[2 * kg][3]);
                pa[2] = pack2(sacc[2 * kg + 1][0], sacc[2 * kg + 1][1]);
                pa[3] = pack2(sacc[2 * kg + 1][2], sacc[2 * kg + 1][3]);
#pragma unroll
                for (int nt = 0; nt < 8; nt++) {
                    const uint2 bb = *(const uint2*)(vfb + ((nt * 4 + kg) * 32 + lane) * 2);
                    mma_f16(o[mt][nt], pa, bb.x, bb.y);
                }
            }

            if (mt == 0 && more) stage_to(s ^ 1);
        }
        __syncthreads();
    }

    // ---- epilogue: y = O / l
#pragma unroll
    for (int mt = 0; mt < 2; mt++) {
        const float inv0 = 1.f / l[mt][0];
        const float inv1 = 1.f / l[mt][1];
        const int tq = qt * 64 + tw + mt * 16 + lr;
        float* y0 = y + (((size_t)b * TT + tq) * NQH + h) * HD;
        float* y1 = y + (((size_t)b * TT + tq + 8) * NQH + h) * HD;
#pragma unroll
        for (int nt = 0; nt < 8; nt++) {
            const int col = nt * 8 + 2 * lc;
            *(float2*)(y0 + col) = make_float2(o[mt][nt][0] * inv0, o[mt][nt][1] * inv0);
            *(float2*)(y1 + col) = make_float2(o[mt][nt][2] * inv1, o[mt][nt][3] * inv1);
        }
    }
}

// ---------------------------------------------------------------------------
extern "C" void kernel_launch(void* const* d_in, const int* in_sizes, int n_in,
                              void* d_out, int out_size)
{
    const float* x  = (const float*)d_in[0];
    const float* Wq = (const float*)d_in[1];
    const float* bq = (const float*)d_in[2];
    const float* Wk = (const float*)d_in[3];
    const float* bk = (const float*)d_in[4];
    const float* Wv = (const float*)d_in[5];
    const float* bv = (const float*)d_in[6];
    const float* Wo = (const float*)d_in[7];
    const float* bo = (const float*)d_in[8];
    float* out = (float*)d_out;

    float *qp, *kp, *vp, *yp;
    __half *qh, *kh, *vth;
    cudaGetSymbolAddress((void**)&qp, g_q);
    cudaGetSymbolAddress((void**)&kp, g_k);
    cudaGetSymbolAddress((void**)&vp, g_v);
    cudaGetSymbolAddress((void**)&yp, g_y);
    cudaGetSymbolAddress((void**)&qh, g_qh);
    cudaGetSymbolAddress((void**)&kh, g_kh);
    cudaGetSymbolAddress((void**)&vth, g_vth);

    cudaFuncSetAttribute(gemm_tc, cudaFuncAttributeMaxDynamicSharedMemorySize, GEMM_SMEM);
    cudaFuncSetAttribute(attn_tc, cudaFuncAttributeMaxDynamicSharedMemorySize, ATTN_SMEM);

    // QKV projections (HMMA fp16, f32 accumulate)
    gemm_tc<<<dim3(EMB / 128, MTOT / 128), 256, GEMM_SMEM>>>(x, Wq, bq, qp, MTOT, EMB, EMB);
    gemm_tc<<<dim3(KVD / 128, MTOT / 128), 256, GEMM_SMEM>>>(x, Wk, bk, kp, MTOT, KVD, EMB);
    gemm_tc<<<dim3(KVD / 128, MTOT / 128), 256, GEMM_SMEM>>>(x, Wv, bv, vp, MTOT, KVD, EMB);

    // RoPE (q scaled by 0.125*log2e) + V transpose
    {
        long nmax = (long)BB * TT * NQH * 32;
        int blocks = (int)((nmax + 255) / 256);
        rope_kernel<<<dim3(blocks, 2), 256>>>(qp, kp, qh, kh);
    }
    vt_kernel<<<dim3(TT / 32, NKV, BB), 256>>>(vp, vth);

    // Causal GQA flash attention (fp16 HMMA, 4 heads per CTA)
    attn_tc<<<dim3(TT / 64, NKV, BB), 256, ATTN_SMEM>>>(qh, kh, vth, yp);

    // Output projection (HMMA fp16)
    gemm_tc<<<dim3(EMB / 128, MTOT / 128), 256, GEMM_SMEM>>>(yp, Wo, bo, out, MTOT, EMB, EMB);
}